// round 2
// baseline (speedup 1.0000x reference)
#include <cuda_runtime.h>
#include <cuda_bf16.h>

// ---------------------------------------------------------------------------
// CoAttention: B=8, NV=NQ=512, D=512, H=8, dh=64, DF=2048, L=4
// Round 1: fp32 throughout. Tiled SGEMM (128x128x8, 8x8/thread), specialized
// attention kernels, fused residual+LN, fused masked softmax.
// ---------------------------------------------------------------------------

#define BB    8
#define NS    512
#define DM    512
#define NHEAD 8
#define DHH   64
#define DFF   2048
#define NLAY  4
#define LN_EPS 1e-5f

// ------------------------------- scratch -----------------------------------
__device__ float g_v [BB*NS*DM];
__device__ float g_q [BB*NS*DM];
__device__ float g_pq[BB*NS*DM];
__device__ float g_pk[BB*NS*DM];
__device__ float g_pv[BB*NS*DM];
__device__ float g_sc[BB*NHEAD*NS*NS];   // 64 MB
__device__ float g_ao[BB*NS*DM];
__device__ float g_tmp[BB*NS*DM];
__device__ float g_va[BB*NS*DM];
__device__ float g_qa[BB*NS*DM];
__device__ float g_vq[BB*NS*DM];
__device__ float g_qv[BB*NS*DM];
__device__ float g_ffn[BB*NS*DFF];       // 32 MB

// ------------------------------- kernels -----------------------------------

__global__ void copy_k(const float* __restrict__ src, float* __restrict__ dst, int n) {
    int i = blockIdx.x * blockDim.x + threadIdx.x;
    if (i < n) dst[i] = src[i];
}

// C[M,N] = A[M,K] @ B[K,N] (+bias)(+relu), batched via grid.z + strides.
// BM=BN=128, BK=8, 256 threads, 8x8 per thread. All dims multiples of tiles.
__global__ __launch_bounds__(256) void sgemm_nn(
    const float* __restrict__ A, const float* __restrict__ Bm,
    const float* __restrict__ bias, float* __restrict__ C,
    int M, int N, int K,
    long long sA, long long sB, long long sC, int relu)
{
    int zb = blockIdx.z;
    A  += (long long)zb * sA;
    Bm += (long long)zb * sB;
    C  += (long long)zb * sC;

    __shared__ float As[8][128];
    __shared__ float Bs[8][128];

    const int tid = threadIdx.x;
    const int tx = tid & 15, ty = tid >> 4;
    const int row0 = blockIdx.y * 128;
    const int col0 = blockIdx.x * 128;

    float acc[8][8];
    #pragma unroll
    for (int i = 0; i < 8; i++)
        #pragma unroll
        for (int j = 0; j < 8; j++) acc[i][j] = 0.f;

    const int arow = tid >> 1;
    const int akk  = (tid & 1) * 4;
    const int bkk  = tid >> 5;
    const int bcol = (tid & 31) * 4;

    for (int k0 = 0; k0 < K; k0 += 8) {
        float4 a4 = *(const float4*)(A + (long long)(row0 + arow) * K + k0 + akk);
        As[akk + 0][arow] = a4.x;
        As[akk + 1][arow] = a4.y;
        As[akk + 2][arow] = a4.z;
        As[akk + 3][arow] = a4.w;
        float4 b4 = *(const float4*)(Bm + (long long)(k0 + bkk) * N + col0 + bcol);
        *(float4*)(&Bs[bkk][bcol]) = b4;
        __syncthreads();
        #pragma unroll
        for (int kk = 0; kk < 8; kk++) {
            float ra[8], rb[8];
            #pragma unroll
            for (int i = 0; i < 8; i++) ra[i] = As[kk][ty * 8 + i];
            #pragma unroll
            for (int j = 0; j < 8; j++) rb[j] = Bs[kk][tx * 8 + j];
            #pragma unroll
            for (int i = 0; i < 8; i++)
                #pragma unroll
                for (int j = 0; j < 8; j++)
                    acc[i][j] = fmaf(ra[i], rb[j], acc[i][j]);
        }
        __syncthreads();
    }

    #pragma unroll
    for (int i = 0; i < 8; i++) {
        int r = row0 + ty * 8 + i;
        #pragma unroll
        for (int j = 0; j < 8; j += 4) {
            int c = col0 + tx * 8 + j;
            float4 o;
            o.x = acc[i][j + 0]; o.y = acc[i][j + 1];
            o.z = acc[i][j + 2]; o.w = acc[i][j + 3];
            if (bias) {
                o.x += bias[c + 0]; o.y += bias[c + 1];
                o.z += bias[c + 2]; o.w += bias[c + 3];
            }
            if (relu) {
                o.x = fmaxf(o.x, 0.f); o.y = fmaxf(o.y, 0.f);
                o.z = fmaxf(o.z, 0.f); o.w = fmaxf(o.w, 0.f);
            }
            *(float4*)(C + (long long)r * N + c) = o;
        }
    }
}

// C[i,j] = sum_k A[i,k] * B[j,k], batched (final bilinear scores).
__global__ __launch_bounds__(256) void sgemm_nt(
    const float* __restrict__ A, const float* __restrict__ Bm,
    float* __restrict__ C,
    int M, int N, int K,
    long long sA, long long sB, long long sC)
{
    int zb = blockIdx.z;
    A  += (long long)zb * sA;
    Bm += (long long)zb * sB;
    C  += (long long)zb * sC;

    __shared__ float As[8][128];
    __shared__ float Bs[8][128];

    const int tid = threadIdx.x;
    const int tx = tid & 15, ty = tid >> 4;
    const int row0 = blockIdx.y * 128;
    const int col0 = blockIdx.x * 128;

    float acc[8][8];
    #pragma unroll
    for (int i = 0; i < 8; i++)
        #pragma unroll
        for (int j = 0; j < 8; j++) acc[i][j] = 0.f;

    const int lrow = tid >> 1;
    const int lkk  = (tid & 1) * 4;

    for (int k0 = 0; k0 < K; k0 += 8) {
        float4 a4 = *(const float4*)(A + (long long)(row0 + lrow) * K + k0 + lkk);
        As[lkk + 0][lrow] = a4.x;
        As[lkk + 1][lrow] = a4.y;
        As[lkk + 2][lrow] = a4.z;
        As[lkk + 3][lrow] = a4.w;
        float4 b4 = *(const float4*)(Bm + (long long)(col0 + lrow) * K + k0 + lkk);
        Bs[lkk + 0][lrow] = b4.x;
        Bs[lkk + 1][lrow] = b4.y;
        Bs[lkk + 2][lrow] = b4.z;
        Bs[lkk + 3][lrow] = b4.w;
        __syncthreads();
        #pragma unroll
        for (int kk = 0; kk < 8; kk++) {
            float ra[8], rb[8];
            #pragma unroll
            for (int i = 0; i < 8; i++) ra[i] = As[kk][ty * 8 + i];
            #pragma unroll
            for (int j = 0; j < 8; j++) rb[j] = Bs[kk][tx * 8 + j];
            #pragma unroll
            for (int i = 0; i < 8; i++)
                #pragma unroll
                for (int j = 0; j < 8; j++)
                    acc[i][j] = fmaf(ra[i], rb[j], acc[i][j]);
        }
        __syncthreads();
    }

    #pragma unroll
    for (int i = 0; i < 8; i++) {
        int r = row0 + ty * 8 + i;
        #pragma unroll
        for (int j = 0; j < 8; j += 4) {
            int c = col0 + tx * 8 + j;
            float4 o;
            o.x = acc[i][j + 0]; o.y = acc[i][j + 1];
            o.z = acc[i][j + 2]; o.w = acc[i][j + 3];
            *(float4*)(C + (long long)r * N + c) = o;
        }
    }
}

// S[b,h,i,j] = scale * dot64(Q[b,i,h*64:], K[b,j,h*64:])
// grid (N/64, N/64, B*H), 256 threads, 4x4 per thread.
__global__ __launch_bounds__(256) void attn_scores(
    const float* __restrict__ Q, const float* __restrict__ K,
    float* __restrict__ S, float scale)
{
    int bh = blockIdx.z;
    int b = bh >> 3, h = bh & 7;
    const float* Qp = Q + (long long)b * NS * DM + h * DHH;
    const float* Kp = K + (long long)b * NS * DM + h * DHH;
    float* Sp = S + (long long)bh * NS * NS;
    int i0 = blockIdx.y * 64, j0 = blockIdx.x * 64;

    __shared__ float Qs[64][65];   // [c][row]
    __shared__ float Ks[64][65];

    int tid = threadIdx.x, tx = tid & 15, ty = tid >> 4;

    #pragma unroll
    for (int r = 0; r < 4; r++) {
        int row = ty + r * 16;
        float4 qa = *(const float4*)(Qp + (long long)(i0 + row) * DM + tx * 4);
        Qs[tx * 4 + 0][row] = qa.x;
        Qs[tx * 4 + 1][row] = qa.y;
        Qs[tx * 4 + 2][row] = qa.z;
        Qs[tx * 4 + 3][row] = qa.w;
        float4 ka = *(const float4*)(Kp + (long long)(j0 + row) * DM + tx * 4);
        Ks[tx * 4 + 0][row] = ka.x;
        Ks[tx * 4 + 1][row] = ka.y;
        Ks[tx * 4 + 2][row] = ka.z;
        Ks[tx * 4 + 3][row] = ka.w;
    }
    __syncthreads();

    float acc[4][4];
    #pragma unroll
    for (int i = 0; i < 4; i++)
        #pragma unroll
        for (int j = 0; j < 4; j++) acc[i][j] = 0.f;

    #pragma unroll 8
    for (int c = 0; c < 64; c++) {
        float ra[4], rb[4];
        #pragma unroll
        for (int i = 0; i < 4; i++) ra[i] = Qs[c][ty * 4 + i];
        #pragma unroll
        for (int j = 0; j < 4; j++) rb[j] = Ks[c][tx * 4 + j];
        #pragma unroll
        for (int i = 0; i < 4; i++)
            #pragma unroll
            for (int j = 0; j < 4; j++)
                acc[i][j] = fmaf(ra[i], rb[j], acc[i][j]);
    }

    #pragma unroll
    for (int i = 0; i < 4; i++)
        #pragma unroll
        for (int j = 0; j < 4; j++)
            Sp[(long long)(i0 + ty * 4 + i) * NS + j0 + tx * 4 + j] = acc[i][j] * scale;
}

// Row softmax with key-padding mask (mask==0 => -1e9). rows = B*H*N, len = N.
__global__ __launch_bounds__(256) void softmax_attn(
    float* __restrict__ S, const int* __restrict__ mask)
{
    int row = blockIdx.x;            // 0 .. B*H*N-1
    int b = row >> 12;               // / (H*N)
    float* Sp = S + (long long)row * NS;
    const int* mp = mask + b * NS;
    int tid = threadIdx.x;

    float v0 = mp[tid]       ? Sp[tid]       : -1e9f;
    float v1 = mp[tid + 256] ? Sp[tid + 256] : -1e9f;

    __shared__ float red[256];
    red[tid] = fmaxf(v0, v1);
    __syncthreads();
    for (int s = 128; s > 0; s >>= 1) {
        if (tid < s) red[tid] = fmaxf(red[tid], red[tid + s]);
        __syncthreads();
    }
    float m = red[0];
    __syncthreads();

    float e0 = __expf(v0 - m), e1 = __expf(v1 - m);
    red[tid] = e0 + e1;
    __syncthreads();
    for (int s = 128; s > 0; s >>= 1) {
        if (tid < s) red[tid] += red[tid + s];
        __syncthreads();
    }
    float inv = 1.f / red[0];
    Sp[tid]       = e0 * inv;
    Sp[tid + 256] = e1 * inv;
}

// O[b,i,h*64+c] = sum_j A[b,h,i,j] * V[b,j,h*64+c]
// grid (N/64, B*H), 256 threads, 4x4 per thread over (i, c).
__global__ __launch_bounds__(256) void attn_av(
    const float* __restrict__ A, const float* __restrict__ V, float* __restrict__ O)
{
    int bh = blockIdx.y;
    int b = bh >> 3, h = bh & 7;
    int i0 = blockIdx.x * 64;
    const float* Ap = A + (long long)bh * NS * NS;
    const float* Vp = V + (long long)b * NS * DM + h * DHH;

    __shared__ float As[16][65];   // [j][i]
    __shared__ float Vs[16][68];   // [j][c], stride 68 keeps float4 stores aligned

    int tid = threadIdx.x, tx = tid & 15, ty = tid >> 4;
    float acc[4][4];
    #pragma unroll
    for (int i = 0; i < 4; i++)
        #pragma unroll
        for (int j = 0; j < 4; j++) acc[i][j] = 0.f;

    for (int j0 = 0; j0 < NS; j0 += 16) {
        int ar = tid >> 2, ac = (tid & 3) * 4;
        float4 a4 = *(const float4*)(Ap + (long long)(i0 + ar) * NS + j0 + ac);
        As[ac + 0][ar] = a4.x;
        As[ac + 1][ar] = a4.y;
        As[ac + 2][ar] = a4.z;
        As[ac + 3][ar] = a4.w;
        int vr = tid >> 4, vc = (tid & 15) * 4;
        float4 v4 = *(const float4*)(Vp + (long long)(j0 + vr) * DM + vc);
        *(float4*)(&Vs[vr][vc]) = v4;
        __syncthreads();
        #pragma unroll
        for (int kk = 0; kk < 16; kk++) {
            float ra[4], rv[4];
            #pragma unroll
            for (int i = 0; i < 4; i++) ra[i] = As[kk][ty * 4 + i];
            #pragma unroll
            for (int j = 0; j < 4; j++) rv[j] = Vs[kk][tx * 4 + j];
            #pragma unroll
            for (int i = 0; i < 4; i++)
                #pragma unroll
                for (int j = 0; j < 4; j++)
                    acc[i][j] = fmaf(ra[i], rv[j], acc[i][j]);
        }
        __syncthreads();
    }

    #pragma unroll
    for (int i = 0; i < 4; i++)
        #pragma unroll
        for (int j = 0; j < 4; j++)
            O[(long long)(b * NS + i0 + ty * 4 + i) * DM + h * DHH + tx * 4 + j] = acc[i][j];
}

// out[row] = LN(x[row] + y[row]) * g + b.  rows = B*N, D = 512, 256 threads.
__global__ __launch_bounds__(256) void ln_add(
    const float* __restrict__ X, const float* __restrict__ Y,
    const float* __restrict__ g, const float* __restrict__ be,
    float* __restrict__ O)
{
    int row = blockIdx.x;
    const float* xp = X + (long long)row * DM;
    const float* yp = Y + (long long)row * DM;
    float* op = O + (long long)row * DM;
    int tid = threadIdx.x;

    float a0 = xp[tid] + yp[tid];
    float a1 = xp[tid + 256] + yp[tid + 256];

    __shared__ float r1[256];
    __shared__ float r2[256];
    r1[tid] = a0 + a1;
    r2[tid] = a0 * a0 + a1 * a1;
    __syncthreads();
    for (int s = 128; s > 0; s >>= 1) {
        if (tid < s) { r1[tid] += r1[tid + s]; r2[tid] += r2[tid + s]; }
        __syncthreads();
    }
    float mean = r1[0] * (1.f / DM);
    float var  = r2[0] * (1.f / DM) - mean * mean;
    float rstd = rsqrtf(var + LN_EPS);
    op[tid]       = (a0 - mean) * rstd * g[tid]       + be[tid];
    op[tid + 256] = (a1 - mean) * rstd * g[tid + 256] + be[tid + 256];
}

// vw[b,i,k] = v[b,i,k] * att_w[k]
__global__ void vmul_k(const float* __restrict__ v, const float* __restrict__ w,
                       float* __restrict__ o, int n) {
    int i = blockIdx.x * blockDim.x + threadIdx.x;
    if (i < n) o[i] = v[i] * w[i & (DM - 1)];
}

// Final softmax over q-axis with cross mask; rows = B*NV.
__global__ __launch_bounds__(256) void softmax_final(
    float* __restrict__ S, const int* __restrict__ vmask,
    const int* __restrict__ qmask, const float* __restrict__ attb)
{
    int row = blockIdx.x;
    int b = row >> 9, i = row & (NS - 1);
    int rowpad = (vmask[b * NS + i] == 0);
    float ab = attb[0];
    float* Sp = S + (long long)row * NS;
    int tid = threadIdx.x;

    float v0 = (rowpad || qmask[b * NS + tid] == 0)       ? -1e9f : Sp[tid] + ab;
    float v1 = (rowpad || qmask[b * NS + tid + 256] == 0) ? -1e9f : Sp[tid + 256] + ab;

    __shared__ float red[256];
    red[tid] = fmaxf(v0, v1);
    __syncthreads();
    for (int s = 128; s > 0; s >>= 1) {
        if (tid < s) red[tid] = fmaxf(red[tid], red[tid + s]);
        __syncthreads();
    }
    float m = red[0];
    __syncthreads();

    float e0 = __expf(v0 - m), e1 = __expf(v1 - m);
    red[tid] = e0 + e1;
    __syncthreads();
    for (int s = 128; s > 0; s >>= 1) {
        if (tid < s) red[tid] += red[tid + s];
        __syncthreads();
    }
    float inv = 1.f / red[0];
    Sp[tid]       = e0 * inv;
    Sp[tid + 256] = e1 * inv;
}

// out[b,k] = (1/512) * sum_i V[b,i,k] * T[b,i,k]
__global__ void final_out_k(const float* __restrict__ V, const float* __restrict__ T,
                            float* __restrict__ out) {
    int b = blockIdx.x;
    int k = threadIdx.x;      // 512
    const float* vp = V + (long long)b * NS * DM;
    const float* tp = T + (long long)b * NS * DM;
    float acc = 0.f;
    #pragma unroll 4
    for (int i = 0; i < NS; i++)
        acc = fmaf(vp[(long long)i * DM + k], tp[(long long)i * DM + k], acc);
    out[b * DM + k] = acc * (1.f / 512.f);
}

// ------------------------------- host side ---------------------------------

static void run_mha(const float* xq, const float* xkv, const int* mask,
                    const float* w, const float* b,
                    const float* wo, const float* bo,
                    float* PQ, float* PK, float* PV, float* SC, float* AO,
                    float* out)
{
    dim3 gP(DM / 128, (BB * NS) / 128, 1);
    sgemm_nn<<<gP, 256>>>(xq,  w,                b,          PQ, BB * NS, DM, DM, 0, 0, 0, 0);
    sgemm_nn<<<gP, 256>>>(xkv, w + DM * DM,      b + DM,     PK, BB * NS, DM, DM, 0, 0, 0, 0);
    sgemm_nn<<<gP, 256>>>(xkv, w + 2 * DM * DM,  b + 2 * DM, PV, BB * NS, DM, DM, 0, 0, 0, 0);
    attn_scores<<<dim3(NS / 64, NS / 64, BB * NHEAD), 256>>>(PQ, PK, SC, 0.125f);
    softmax_attn<<<BB * NHEAD * NS, 256>>>(SC, mask);
    attn_av<<<dim3(NS / 64, BB * NHEAD), 256>>>(SC, PV, AO);
    sgemm_nn<<<gP, 256>>>(AO, wo, bo, out, BB * NS, DM, DM, 0, 0, 0, 0);
}

extern "C" void kernel_launch(void* const* d_in, const int* in_sizes, int n_in,
                              void* d_out, int out_size)
{
    // Resolve input ordering: dict order (masks at idx 2,3) vs signature order.
    const float *v_in, *q_in, *attn_w, *attn_b, *attn_wo, *attn_bo;
    const float *ln_g, *ln_b, *fw1, *fb1, *fw2, *fb2, *att_w, *att_b;
    const int *v_mask, *q_mask;

    if (in_sizes[2] == BB * NS) {   // dict order: v,q,v_mask,q_mask,weights...
        v_in    = (const float*)d_in[0];
        q_in    = (const float*)d_in[1];
        v_mask  = (const int*)  d_in[2];
        q_mask  = (const int*)  d_in[3];
        attn_w  = (const float*)d_in[4];
        attn_b  = (const float*)d_in[5];
        attn_wo = (const float*)d_in[6];
        attn_bo = (const float*)d_in[7];
        ln_g    = (const float*)d_in[8];
        ln_b    = (const float*)d_in[9];
        fw1     = (const float*)d_in[10];
        fb1     = (const float*)d_in[11];
        fw2     = (const float*)d_in[12];
        fb2     = (const float*)d_in[13];
        att_w   = (const float*)d_in[14];
        att_b   = (const float*)d_in[15];
    } else {                        // signature order: v,q,weights...,v_mask,q_mask
        v_in    = (const float*)d_in[0];
        q_in    = (const float*)d_in[1];
        attn_w  = (const float*)d_in[2];
        attn_b  = (const float*)d_in[3];
        attn_wo = (const float*)d_in[4];
        attn_bo = (const float*)d_in[5];
        ln_g    = (const float*)d_in[6];
        ln_b    = (const float*)d_in[7];
        fw1     = (const float*)d_in[8];
        fb1     = (const float*)d_in[9];
        fw2     = (const float*)d_in[10];
        fb2     = (const float*)d_in[11];
        att_w   = (const float*)d_in[12];
        att_b   = (const float*)d_in[13];
        v_mask  = (const int*)  d_in[14];
        q_mask  = (const int*)  d_in[15];
    }

    float *V, *Q, *PQ, *PK, *PV, *SC, *AO, *TMP, *VA, *QA, *VQ, *QV, *FFN;
    cudaGetSymbolAddress((void**)&V,   g_v);
    cudaGetSymbolAddress((void**)&Q,   g_q);
    cudaGetSymbolAddress((void**)&PQ,  g_pq);
    cudaGetSymbolAddress((void**)&PK,  g_pk);
    cudaGetSymbolAddress((void**)&PV,  g_pv);
    cudaGetSymbolAddress((void**)&SC,  g_sc);
    cudaGetSymbolAddress((void**)&AO,  g_ao);
    cudaGetSymbolAddress((void**)&TMP, g_tmp);
    cudaGetSymbolAddress((void**)&VA,  g_va);
    cudaGetSymbolAddress((void**)&QA,  g_qa);
    cudaGetSymbolAddress((void**)&VQ,  g_vq);
    cudaGetSymbolAddress((void**)&QV,  g_qv);
    cudaGetSymbolAddress((void**)&FFN, g_ffn);

    const int NTOK = BB * NS * DM;
    copy_k<<<(NTOK + 255) / 256, 256>>>(v_in, V, NTOK);
    copy_k<<<(NTOK + 255) / 256, 256>>>(q_in, Q, NTOK);

    const int rows = BB * NS;
    dim3 gFF1(DFF / 128, rows / 128, 1);
    dim3 gFF2(DM / 128, rows / 128, 1);

    for (int i = 0; i < NLAY; i++) {
        const float* aw  = attn_w  + (long long)i * 4 * 3 * DM * DM;
        const float* ab  = attn_b  + (long long)i * 4 * 3 * DM;
        const float* awo = attn_wo + (long long)i * 4 * DM * DM;
        const float* abo = attn_bo + (long long)i * 4 * DM;
        const float* lg  = ln_g + (long long)i * 6 * DM;
        const float* lb  = ln_b + (long long)i * 6 * DM;

        // self-attn v -> v_a
        run_mha(V, V, v_mask, aw, ab, awo, abo, PQ, PK, PV, SC, AO, TMP);
        ln_add<<<rows, 256>>>(V, TMP, lg, lb, VA);
        // self-attn q -> q_a
        run_mha(Q, Q, q_mask,
                aw + 3 * DM * DM, ab + 3 * DM, awo + DM * DM, abo + DM,
                PQ, PK, PV, SC, AO, TMP);
        ln_add<<<rows, 256>>>(Q, TMP, lg + DM, lb + DM, QA);
        // cross: vq_out = mha(v_a, q_a, q_pad)
        run_mha(VA, QA, q_mask,
                aw + 6 * DM * DM, ab + 6 * DM, awo + 2 * DM * DM, abo + 2 * DM,
                PQ, PK, PV, SC, AO, VQ);
        // cross: qv_out = mha(q_a, vq_out, v_pad)
        run_mha(QA, VQ, v_mask,
                aw + 9 * DM * DM, ab + 9 * DM, awo + 3 * DM * DM, abo + 3 * DM,
                PQ, PK, PV, SC, AO, QV);
        // residual + LN
        ln_add<<<rows, 256>>>(V, VQ, lg + 2 * DM, lb + 2 * DM, V);
        ln_add<<<rows, 256>>>(Q, QV, lg + 3 * DM, lb + 3 * DM, Q);

        // FFN v
        const float* w1v = fw1 + (long long)i * 2 * DM * DFF;
        const float* b1v = fb1 + (long long)i * 2 * DFF;
        const float* w2v = fw2 + (long long)i * 2 * DFF * DM;
        const float* b2v = fb2 + (long long)i * 2 * DM;
        sgemm_nn<<<gFF1, 256>>>(V, w1v, b1v, FFN, rows, DFF, DM, 0, 0, 0, 1);
        sgemm_nn<<<gFF2, 256>>>(FFN, w2v, b2v, TMP, rows, DM, DFF, 0, 0, 0, 0);
        ln_add<<<rows, 256>>>(V, TMP, lg + 4 * DM, lb + 4 * DM, V);
        // FFN q
        sgemm_nn<<<gFF1, 256>>>(Q, w1v + DM * DFF, b1v + DFF, FFN, rows, DFF, DM, 0, 0, 0, 1);
        sgemm_nn<<<gFF2, 256>>>(FFN, w2v + DFF * DM, b2v + DM, TMP, rows, DM, DFF, 0, 0, 0, 0);
        ln_add<<<rows, 256>>>(Q, TMP, lg + 5 * DM, lb + 5 * DM, Q);
    }

    // Final bilinear attention pooling.
    vmul_k<<<(NTOK + 255) / 256, 256>>>(V, att_w, PQ, NTOK);   // PQ = V * att_w
    // s[b] = PQ[b] @ Q[b]^T   -> SC  (batched NT)
    sgemm_nt<<<dim3(NS / 128, NS / 128, BB), 256>>>(
        PQ, Q, SC, NS, NS, DM,
        (long long)NS * DM, (long long)NS * DM, (long long)NS * NS);
    softmax_final<<<BB * NS, 256>>>(SC, v_mask, q_mask, att_b);
    // T[b] = SC[b] @ Q[b]     -> PK  (batched NN)
    sgemm_nn<<<dim3(DM / 128, NS / 128, BB), 256>>>(
        SC, Q, (const float*)nullptr, PK, NS, DM, NS,
        (long long)NS * NS, (long long)NS * DM, (long long)NS * DM, 0);
    final_out_k<<<BB, 512>>>(V, PK, (float*)d_out);
}

// round 6
// speedup vs baseline: 2.0560x; 2.0560x over previous
#include <cuda_runtime.h>
#include <cuda_bf16.h>

// ---------------------------------------------------------------------------
// CoAttention R3: all GEMMs on tensor pipe via mma.sync m16n8k8 tf32.
// R2 + fix: final bilinear launches used NT (full tensor) as per-batch stride.
// B=8, NV=NQ=512, D=512, H=8, dh=64, DF=2048, L=4
// ---------------------------------------------------------------------------

#define BB    8
#define NS    512
#define DM    512
#define NHEAD 8
#define DHH   64
#define DFF   2048
#define NLAY  4
#define LN_EPS 1e-5f

// ------------------------------- scratch -----------------------------------
__device__ float g_v  [BB*NS*DM];
__device__ float g_q  [BB*NS*DM];
__device__ float g_qkv[3*BB*NS*DM];      // fused QKV projections / final scratch
__device__ float g_sc [BB*NHEAD*NS*NS];  // 64 MB scores
__device__ float g_ao [BB*NS*DM];
__device__ float g_tmp[BB*NS*DM];
__device__ float g_va [BB*NS*DM];
__device__ float g_qa [BB*NS*DM];
__device__ float g_vq [BB*NS*DM];
__device__ float g_qv [BB*NS*DM];
__device__ float g_ffn[BB*NS*DFF];       // 32 MB

// ------------------------------- helpers -----------------------------------

__device__ __forceinline__ float to_tf32(float x) {
    unsigned u;
    asm("cvt.rna.tf32.f32 %0, %1;" : "=r"(u) : "f"(x));
    return __uint_as_float(u);
}

__device__ __forceinline__ void mma1688(float* c, const unsigned* a, const unsigned* b) {
    asm volatile(
        "mma.sync.aligned.m16n8k8.row.col.f32.tf32.tf32.f32 "
        "{%0,%1,%2,%3}, {%4,%5,%6,%7}, {%8,%9}, {%0,%1,%2,%3};\n"
        : "+f"(c[0]), "+f"(c[1]), "+f"(c[2]), "+f"(c[3])
        : "r"(a[0]), "r"(a[1]), "r"(a[2]), "r"(a[3]), "r"(b[0]), "r"(b[1]));
}

// ------------------------------- kernels -----------------------------------

__global__ void copy_k(const float* __restrict__ src, float* __restrict__ dst, int n) {
    int i = blockIdx.x * blockDim.x + threadIdx.x;
    if (i < n) dst[i] = src[i];
}

// NN GEMM: C[M,N] = A[M,K] @ B[K,N] (+bias)(+relu). tf32 tensor cores.
// Block tile 128x64, BK=16, 256 threads = 8 warps (4x2), warp tile 32x32.
// Batched via grid.z with split-stride addressing: off = (z/zdiv)*s1 + (z%zdiv)*s2.
__global__ __launch_bounds__(256) void mma_nn(
    const float* __restrict__ A, const float* __restrict__ B,
    const float* __restrict__ bias, float* __restrict__ C,
    int K, int lda, int ldb, int ldc,
    int zdiv, long long sA1, long long sA2, long long sB1, long long sB2,
    long long sC1, long long sC2, long long sBias, int relu)
{
    int z = blockIdx.z;
    int z1 = z / zdiv, z2 = z - z1 * zdiv;
    A += z1 * sA1 + (long long)z2 * sA2;
    B += z1 * sB1 + (long long)z2 * sB2;
    C += z1 * sC1 + (long long)z2 * sC2;
    if (bias) bias += (long long)z * sBias;

    __shared__ float As[2][16][130];   // [k][m]
    __shared__ float Bs[2][16][72];    // [k][n]

    const int tid = threadIdx.x;
    const int wid = tid >> 5, lane = tid & 31;
    const int wm = (wid >> 1) * 32, wn = (wid & 1) * 32;
    const int g = lane >> 2, t4 = lane & 3;
    const int row0 = blockIdx.y * 128, col0 = blockIdx.x * 64;

    const int am = tid >> 2;          // 0..63
    const int ak = (tid & 3) * 4;     // 0,4,8,12
    const int bk = tid >> 4;          // 0..15
    const int bn = (tid & 15) * 4;    // 0..60

    const float* Aptr  = A + (long long)(row0 + am) * lda + ak;
    const float* Aptr2 = Aptr + (long long)64 * lda;
    const float* Bptr  = B + (long long)bk * ldb + col0 + bn;

    float acc[2][4][4];
    #pragma unroll
    for (int mi = 0; mi < 2; mi++)
        #pragma unroll
        for (int ni = 0; ni < 4; ni++)
            #pragma unroll
            for (int r = 0; r < 4; r++) acc[mi][ni][r] = 0.f;

    {
        float4 a0 = *(const float4*)(Aptr);
        float4 a1 = *(const float4*)(Aptr2);
        float4 b0 = *(const float4*)(Bptr);
        As[0][ak + 0][am] = to_tf32(a0.x);
        As[0][ak + 1][am] = to_tf32(a0.y);
        As[0][ak + 2][am] = to_tf32(a0.z);
        As[0][ak + 3][am] = to_tf32(a0.w);
        As[0][ak + 0][am + 64] = to_tf32(a1.x);
        As[0][ak + 1][am + 64] = to_tf32(a1.y);
        As[0][ak + 2][am + 64] = to_tf32(a1.z);
        As[0][ak + 3][am + 64] = to_tf32(a1.w);
        float4 bb;
        bb.x = to_tf32(b0.x); bb.y = to_tf32(b0.y);
        bb.z = to_tf32(b0.z); bb.w = to_tf32(b0.w);
        *(float4*)(&Bs[0][bk][bn]) = bb;
    }
    __syncthreads();

    const int nk = K >> 4;
    for (int t = 0; t < nk; t++) {
        const int buf = t & 1;
        float4 ra, ra2, rb;
        if (t + 1 < nk) {
            int k0 = (t + 1) << 4;
            ra  = *(const float4*)(Aptr + k0);
            ra2 = *(const float4*)(Aptr2 + k0);
            rb  = *(const float4*)(Bptr + (long long)k0 * ldb);
        }

        #pragma unroll
        for (int ks = 0; ks < 16; ks += 8) {
            unsigned af[2][4], bf[4][2];
            #pragma unroll
            for (int mi = 0; mi < 2; mi++) {
                int m = wm + mi * 16 + g;
                af[mi][0] = __float_as_uint(As[buf][ks + t4][m]);
                af[mi][1] = __float_as_uint(As[buf][ks + t4][m + 8]);
                af[mi][2] = __float_as_uint(As[buf][ks + t4 + 4][m]);
                af[mi][3] = __float_as_uint(As[buf][ks + t4 + 4][m + 8]);
            }
            #pragma unroll
            for (int ni = 0; ni < 4; ni++) {
                int n = wn + ni * 8 + g;
                bf[ni][0] = __float_as_uint(Bs[buf][ks + t4][n]);
                bf[ni][1] = __float_as_uint(Bs[buf][ks + t4 + 4][n]);
            }
            #pragma unroll
            for (int mi = 0; mi < 2; mi++)
                #pragma unroll
                for (int ni = 0; ni < 4; ni++)
                    mma1688(acc[mi][ni], af[mi], bf[ni]);
        }

        if (t + 1 < nk) {
            const int nb = (t + 1) & 1;
            As[nb][ak + 0][am] = to_tf32(ra.x);
            As[nb][ak + 1][am] = to_tf32(ra.y);
            As[nb][ak + 2][am] = to_tf32(ra.z);
            As[nb][ak + 3][am] = to_tf32(ra.w);
            As[nb][ak + 0][am + 64] = to_tf32(ra2.x);
            As[nb][ak + 1][am + 64] = to_tf32(ra2.y);
            As[nb][ak + 2][am + 64] = to_tf32(ra2.z);
            As[nb][ak + 3][am + 64] = to_tf32(ra2.w);
            float4 bb;
            bb.x = to_tf32(rb.x); bb.y = to_tf32(rb.y);
            bb.z = to_tf32(rb.z); bb.w = to_tf32(rb.w);
            *(float4*)(&Bs[nb][bk][bn]) = bb;
            __syncthreads();
        }
    }

    #pragma unroll
    for (int mi = 0; mi < 2; mi++)
        #pragma unroll
        for (int ni = 0; ni < 4; ni++) {
            int r = row0 + wm + mi * 16 + g;
            int c = col0 + wn + ni * 8 + 2 * t4;
            float b0v = 0.f, b1v = 0.f;
            if (bias) { b0v = bias[c]; b1v = bias[c + 1]; }
            float o0 = acc[mi][ni][0] + b0v;
            float o1 = acc[mi][ni][1] + b1v;
            float o2 = acc[mi][ni][2] + b0v;
            float o3 = acc[mi][ni][3] + b1v;
            if (relu) {
                o0 = fmaxf(o0, 0.f); o1 = fmaxf(o1, 0.f);
                o2 = fmaxf(o2, 0.f); o3 = fmaxf(o3, 0.f);
            }
            *(float2*)(C + (long long)r * ldc + c)       = make_float2(o0, o1);
            *(float2*)(C + (long long)(r + 8) * ldc + c) = make_float2(o2, o3);
        }
}

// NT GEMM: C[M,N] = scale * A[M,K] @ B[N,K]^T. Same tiling as mma_nn.
__global__ __launch_bounds__(256) void mma_nt(
    const float* __restrict__ A, const float* __restrict__ B,
    float* __restrict__ C,
    int K, int lda, int ldb, int ldc,
    int zdiv, long long sA1, long long sA2, long long sB1, long long sB2,
    long long sC1, long long sC2, float scale)
{
    int z = blockIdx.z;
    int z1 = z / zdiv, z2 = z - z1 * zdiv;
    A += z1 * sA1 + (long long)z2 * sA2;
    B += z1 * sB1 + (long long)z2 * sB2;
    C += z1 * sC1 + (long long)z2 * sC2;

    __shared__ float As[2][16][130];
    __shared__ float Bs[2][64][20];

    const int tid = threadIdx.x;
    const int wid = tid >> 5, lane = tid & 31;
    const int wm = (wid >> 1) * 32, wn = (wid & 1) * 32;
    const int g = lane >> 2, t4 = lane & 3;
    const int row0 = blockIdx.y * 128, col0 = blockIdx.x * 64;

    const int am = tid >> 2;
    const int ak = (tid & 3) * 4;
    const int bnr = tid >> 2;
    const int bk4 = (tid & 3) * 4;

    const float* Aptr  = A + (long long)(row0 + am) * lda + ak;
    const float* Aptr2 = Aptr + (long long)64 * lda;
    const float* Bptr  = B + (long long)(col0 + bnr) * ldb + bk4;

    float acc[2][4][4];
    #pragma unroll
    for (int mi = 0; mi < 2; mi++)
        #pragma unroll
        for (int ni = 0; ni < 4; ni++)
            #pragma unroll
            for (int r = 0; r < 4; r++) acc[mi][ni][r] = 0.f;

    {
        float4 a0 = *(const float4*)(Aptr);
        float4 a1 = *(const float4*)(Aptr2);
        float4 b0 = *(const float4*)(Bptr);
        As[0][ak + 0][am] = to_tf32(a0.x);
        As[0][ak + 1][am] = to_tf32(a0.y);
        As[0][ak + 2][am] = to_tf32(a0.z);
        As[0][ak + 3][am] = to_tf32(a0.w);
        As[0][ak + 0][am + 64] = to_tf32(a1.x);
        As[0][ak + 1][am + 64] = to_tf32(a1.y);
        As[0][ak + 2][am + 64] = to_tf32(a1.z);
        As[0][ak + 3][am + 64] = to_tf32(a1.w);
        float4 bb;
        bb.x = to_tf32(b0.x); bb.y = to_tf32(b0.y);
        bb.z = to_tf32(b0.z); bb.w = to_tf32(b0.w);
        *(float4*)(&Bs[0][bnr][bk4]) = bb;
    }
    __syncthreads();

    const int nk = K >> 4;
    for (int t = 0; t < nk; t++) {
        const int buf = t & 1;
        float4 ra, ra2, rb;
        if (t + 1 < nk) {
            int k0 = (t + 1) << 4;
            ra  = *(const float4*)(Aptr + k0);
            ra2 = *(const float4*)(Aptr2 + k0);
            rb  = *(const float4*)(Bptr + k0);
        }

        #pragma unroll
        for (int ks = 0; ks < 16; ks += 8) {
            unsigned af[2][4], bf[4][2];
            #pragma unroll
            for (int mi = 0; mi < 2; mi++) {
                int m = wm + mi * 16 + g;
                af[mi][0] = __float_as_uint(As[buf][ks + t4][m]);
                af[mi][1] = __float_as_uint(As[buf][ks + t4][m + 8]);
                af[mi][2] = __float_as_uint(As[buf][ks + t4 + 4][m]);
                af[mi][3] = __float_as_uint(As[buf][ks + t4 + 4][m + 8]);
            }
            #pragma unroll
            for (int ni = 0; ni < 4; ni++) {
                int n = wn + ni * 8 + g;
                bf[ni][0] = __float_as_uint(Bs[buf][n][ks + t4]);
                bf[ni][1] = __float_as_uint(Bs[buf][n][ks + t4 + 4]);
            }
            #pragma unroll
            for (int mi = 0; mi < 2; mi++)
                #pragma unroll
                for (int ni = 0; ni < 4; ni++)
                    mma1688(acc[mi][ni], af[mi], bf[ni]);
        }

        if (t + 1 < nk) {
            const int nb = (t + 1) & 1;
            As[nb][ak + 0][am] = to_tf32(ra.x);
            As[nb][ak + 1][am] = to_tf32(ra.y);
            As[nb][ak + 2][am] = to_tf32(ra.z);
            As[nb][ak + 3][am] = to_tf32(ra.w);
            As[nb][ak + 0][am + 64] = to_tf32(ra2.x);
            As[nb][ak + 1][am + 64] = to_tf32(ra2.y);
            As[nb][ak + 2][am + 64] = to_tf32(ra2.z);
            As[nb][ak + 3][am + 64] = to_tf32(ra2.w);
            float4 bb;
            bb.x = to_tf32(rb.x); bb.y = to_tf32(rb.y);
            bb.z = to_tf32(rb.z); bb.w = to_tf32(rb.w);
            *(float4*)(&Bs[nb][bnr][bk4]) = bb;
            __syncthreads();
        }
    }

    #pragma unroll
    for (int mi = 0; mi < 2; mi++)
        #pragma unroll
        for (int ni = 0; ni < 4; ni++) {
            int r = row0 + wm + mi * 16 + g;
            int c = col0 + wn + ni * 8 + 2 * t4;
            *(float2*)(C + (long long)r * ldc + c) =
                make_float2(acc[mi][ni][0] * scale, acc[mi][ni][1] * scale);
            *(float2*)(C + (long long)(r + 8) * ldc + c) =
                make_float2(acc[mi][ni][2] * scale, acc[mi][ni][3] * scale);
        }
}

// Row softmax with key-padding mask. rows = B*H*N, len = N.
__global__ __launch_bounds__(256) void softmax_attn(
    float* __restrict__ S, const int* __restrict__ mask)
{
    int row = blockIdx.x;
    int b = row >> 12;
    float* Sp = S + (long long)row * NS;
    const int* mp = mask + b * NS;
    int tid = threadIdx.x;

    float v0 = mp[tid]       ? Sp[tid]       : -1e9f;
    float v1 = mp[tid + 256] ? Sp[tid + 256] : -1e9f;

    __shared__ float red[256];
    red[tid] = fmaxf(v0, v1);
    __syncthreads();
    for (int s = 128; s > 0; s >>= 1) {
        if (tid < s) red[tid] = fmaxf(red[tid], red[tid + s]);
        __syncthreads();
    }
    float m = red[0];
    __syncthreads();

    float e0 = __expf(v0 - m), e1 = __expf(v1 - m);
    red[tid] = e0 + e1;
    __syncthreads();
    for (int s = 128; s > 0; s >>= 1) {
        if (tid < s) red[tid] += red[tid + s];
        __syncthreads();
    }
    float inv = 1.f / red[0];
    Sp[tid]       = e0 * inv;
    Sp[tid + 256] = e1 * inv;
}

// out[row] = LN(x[row] + y[row]) * g + b.
__global__ __launch_bounds__(256) void ln_add(
    const float* __restrict__ X, const float* __restrict__ Y,
    const float* __restrict__ g, const float* __restrict__ be,
    float* __restrict__ O)
{
    int row = blockIdx.x;
    const float* xp = X + (long long)row * DM;
    const float* yp = Y + (long long)row * DM;
    float* op = O + (long long)row * DM;
    int tid = threadIdx.x;

    float a0 = xp[tid] + yp[tid];
    float a1 = xp[tid + 256] + yp[tid + 256];

    __shared__ float r1[256];
    __shared__ float r2[256];
    r1[tid] = a0 + a1;
    r2[tid] = a0 * a0 + a1 * a1;
    __syncthreads();
    for (int s = 128; s > 0; s >>= 1) {
        if (tid < s) { r1[tid] += r1[tid + s]; r2[tid] += r2[tid + s]; }
        __syncthreads();
    }
    float mean = r1[0] * (1.f / DM);
    float var  = r2[0] * (1.f / DM) - mean * mean;
    float rstd = rsqrtf(var + LN_EPS);
    op[tid]       = (a0 - mean) * rstd * g[tid]       + be[tid];
    op[tid + 256] = (a1 - mean) * rstd * g[tid + 256] + be[tid + 256];
}

__global__ void vmul_k(const float* __restrict__ v, const float* __restrict__ w,
                       float* __restrict__ o, int n) {
    int i = blockIdx.x * blockDim.x + threadIdx.x;
    if (i < n) o[i] = v[i] * w[i & (DM - 1)];
}

__global__ __launch_bounds__(256) void softmax_final(
    float* __restrict__ S, const int* __restrict__ vmask,
    const int* __restrict__ qmask, const float* __restrict__ attb)
{
    int row = blockIdx.x;
    int b = row >> 9, i = row & (NS - 1);
    int rowpad = (vmask[b * NS + i] == 0);
    float ab = attb[0];
    float* Sp = S + (long long)row * NS;
    int tid = threadIdx.x;

    float v0 = (rowpad || qmask[b * NS + tid] == 0)       ? -1e9f : Sp[tid] + ab;
    float v1 = (rowpad || qmask[b * NS + tid + 256] == 0) ? -1e9f : Sp[tid + 256] + ab;

    __shared__ float red[256];
    red[tid] = fmaxf(v0, v1);
    __syncthreads();
    for (int s = 128; s > 0; s >>= 1) {
        if (tid < s) red[tid] = fmaxf(red[tid], red[tid + s]);
        __syncthreads();
    }
    float m = red[0];
    __syncthreads();

    float e0 = __expf(v0 - m), e1 = __expf(v1 - m);
    red[tid] = e0 + e1;
    __syncthreads();
    for (int s = 128; s > 0; s >>= 1) {
        if (tid < s) red[tid] += red[tid + s];
        __syncthreads();
    }
    float inv = 1.f / red[0];
    Sp[tid]       = e0 * inv;
    Sp[tid + 256] = e1 * inv;
}

__global__ void final_out_k(const float* __restrict__ V, const float* __restrict__ T,
                            float* __restrict__ out) {
    int b = blockIdx.x;
    int k = threadIdx.x;
    const float* vp = V + (long long)b * NS * DM;
    const float* tp = T + (long long)b * NS * DM;
    float acc = 0.f;
    #pragma unroll 4
    for (int i = 0; i < NS; i++)
        acc = fmaf(vp[(long long)i * DM + k], tp[(long long)i * DM + k], acc);
    out[b * DM + k] = acc * (1.f / 512.f);
}

// ------------------------------- host side ---------------------------------

static void run_mha(const float* xq, const float* xkv, const int* mask,
                    const float* w, const float* b,
                    const float* wo, const float* bo,
                    float* QKV, float* SC, float* AO, float* out)
{
    const long long NT = (long long)BB * NS * DM;
    const long long WSTRIDE = (long long)DM * DM;

    // Q projection (A = xq)
    mma_nn<<<dim3(DM / 64, (BB * NS) / 128, 1), 256>>>(
        xq, w, b, QKV, DM, DM, DM, DM,
        1, 0, 0, 0, 0, 0, 0, DM, 0);
    // K,V projections (A = xkv), z in {0,1} -> weights w[1],w[2]
    mma_nn<<<dim3(DM / 64, (BB * NS) / 128, 2), 256>>>(
        xkv, w + WSTRIDE, b + DM, QKV + NT, DM, DM, DM, DM,
        1, 0, 0, WSTRIDE, 0, NT, 0, DM, 0);

    const float* PQ = QKV;
    const float* PK = QKV + NT;
    const float* PV = QKV + 2 * NT;

    // scores: S[z=b*8+h] = 0.125 * Qh @ Kh^T
    mma_nt<<<dim3(NS / 64, NS / 128, BB * NHEAD), 256>>>(
        PQ, PK, SC, DHH, DM, DM, NS,
        NHEAD, (long long)NS * DM, DHH, (long long)NS * DM, DHH,
        (long long)NHEAD * NS * NS, (long long)NS * NS, 0.125f);

    softmax_attn<<<BB * NHEAD * NS, 256>>>(SC, mask);

    // AV: O_h = S @ V_h   (N = 64)
    mma_nn<<<dim3(1, NS / 128, BB * NHEAD), 256>>>(
        SC, PV, (const float*)nullptr, AO, NS, NS, DM, DM,
        NHEAD, (long long)NHEAD * NS * NS, (long long)NS * NS,
        (long long)NS * DM, DHH,
        (long long)NS * DM, DHH, 0, 0);

    // output projection
    mma_nn<<<dim3(DM / 64, (BB * NS) / 128, 1), 256>>>(
        AO, wo, bo, out, DM, DM, DM, DM,
        1, 0, 0, 0, 0, 0, 0, DM, 0);
}

extern "C" void kernel_launch(void* const* d_in, const int* in_sizes, int n_in,
                              void* d_out, int out_size)
{
    const float *v_in, *q_in, *attn_w, *attn_b, *attn_wo, *attn_bo;
    const float *ln_g, *ln_b, *fw1, *fb1, *fw2, *fb2, *att_w, *att_b;
    const int *v_mask, *q_mask;

    if (in_sizes[2] == BB * NS) {   // dict order: v,q,v_mask,q_mask,weights...
        v_in    = (const float*)d_in[0];
        q_in    = (const float*)d_in[1];
        v_mask  = (const int*)  d_in[2];
        q_mask  = (const int*)  d_in[3];
        attn_w  = (const float*)d_in[4];
        attn_b  = (const float*)d_in[5];
        attn_wo = (const float*)d_in[6];
        attn_bo = (const float*)d_in[7];
        ln_g    = (const float*)d_in[8];
        ln_b    = (const float*)d_in[9];
        fw1     = (const float*)d_in[10];
        fb1     = (const float*)d_in[11];
        fw2     = (const float*)d_in[12];
        fb2     = (const float*)d_in[13];
        att_w   = (const float*)d_in[14];
        att_b   = (const float*)d_in[15];
    } else {                        // signature order
        v_in    = (const float*)d_in[0];
        q_in    = (const float*)d_in[1];
        attn_w  = (const float*)d_in[2];
        attn_b  = (const float*)d_in[3];
        attn_wo = (const float*)d_in[4];
        attn_bo = (const float*)d_in[5];
        ln_g    = (const float*)d_in[6];
        ln_b    = (const float*)d_in[7];
        fw1     = (const float*)d_in[8];
        fb1     = (const float*)d_in[9];
        fw2     = (const float*)d_in[10];
        fb2     = (const float*)d_in[11];
        att_w   = (const float*)d_in[12];
        att_b   = (const float*)d_in[13];
        v_mask  = (const int*)  d_in[14];
        q_mask  = (const int*)  d_in[15];
    }

    float *V, *Q, *QKV, *SC, *AO, *TMP, *VA, *QA, *VQ, *QV, *FFN;
    cudaGetSymbolAddress((void**)&V,   g_v);
    cudaGetSymbolAddress((void**)&Q,   g_q);
    cudaGetSymbolAddress((void**)&QKV, g_qkv);
    cudaGetSymbolAddress((void**)&SC,  g_sc);
    cudaGetSymbolAddress((void**)&AO,  g_ao);
    cudaGetSymbolAddress((void**)&TMP, g_tmp);
    cudaGetSymbolAddress((void**)&VA,  g_va);
    cudaGetSymbolAddress((void**)&QA,  g_qa);
    cudaGetSymbolAddress((void**)&VQ,  g_vq);
    cudaGetSymbolAddress((void**)&QV,  g_qv);
    cudaGetSymbolAddress((void**)&FFN, g_ffn);

    const int NTOK = BB * NS * DM;
    const long long NT = (long long)NTOK;
    const long long SBATCH = (long long)NS * DM;   // per-batch stride
    copy_k<<<(NTOK + 255) / 256, 256>>>(v_in, V, NTOK);
    copy_k<<<(NTOK + 255) / 256, 256>>>(q_in, Q, NTOK);

    const int rows = BB * NS;

    for (int i = 0; i < NLAY; i++) {
        const float* aw  = attn_w  + (long long)i * 4 * 3 * DM * DM;
        const float* ab  = attn_b  + (long long)i * 4 * 3 * DM;
        const float* awo = attn_wo + (long long)i * 4 * DM * DM;
        const float* abo = attn_bo + (long long)i * 4 * DM;
        const float* lg  = ln_g + (long long)i * 6 * DM;
        const float* lb  = ln_b + (long long)i * 6 * DM;

        run_mha(V, V, v_mask, aw, ab, awo, abo, QKV, SC, AO, TMP);
        ln_add<<<rows, 256>>>(V, TMP, lg, lb, VA);

        run_mha(Q, Q, q_mask,
                aw + 3ll * DM * DM, ab + 3 * DM, awo + (long long)DM * DM, abo + DM,
                QKV, SC, AO, TMP);
        ln_add<<<rows, 256>>>(Q, TMP, lg + DM, lb + DM, QA);

        run_mha(VA, QA, q_mask,
                aw + 6ll * DM * DM, ab + 6 * DM, awo + 2ll * DM * DM, abo + 2 * DM,
                QKV, SC, AO, VQ);
        run_mha(QA, VQ, v_mask,
                aw + 9ll * DM * DM, ab + 9 * DM, awo + 3ll * DM * DM, abo + 3 * DM,
                QKV, SC, AO, QV);

        ln_add<<<rows, 256>>>(V, VQ, lg + 2 * DM, lb + 2 * DM, V);
        ln_add<<<rows, 256>>>(Q, QV, lg + 3 * DM, lb + 3 * DM, Q);

        const float* w1v = fw1 + (long long)i * 2 * DM * DFF;
        const float* b1v = fb1 + (long long)i * 2 * DFF;
        const float* w2v = fw2 + (long long)i * 2 * DFF * DM;
        const float* b2v = fb2 + (long long)i * 2 * DM;

        // FFN v
        mma_nn<<<dim3(DFF / 64, rows / 128, 1), 256>>>(
            V, w1v, b1v, FFN, DM, DM, DFF, DFF,
            1, 0, 0, 0, 0, 0, 0, 0, 1);
        mma_nn<<<dim3(DM / 64, rows / 128, 1), 256>>>(
            FFN, w2v, b2v, TMP, DFF, DFF, DM, DM,
            1, 0, 0, 0, 0, 0, 0, 0, 0);
        ln_add<<<rows, 256>>>(V, TMP, lg + 4 * DM, lb + 4 * DM, V);
        // FFN q
        mma_nn<<<dim3(DFF / 64, rows / 128, 1), 256>>>(
            Q, w1v + (long long)DM * DFF, b1v + DFF, FFN, DM, DM, DFF, DFF,
            1, 0, 0, 0, 0, 0, 0, 0, 1);
        mma_nn<<<dim3(DM / 64, rows / 128, 1), 256>>>(
            FFN, w2v + (long long)DFF * DM, b2v + DM, TMP, DFF, DFF, DM, DM,
            1, 0, 0, 0, 0, 0, 0, 0, 0);
        ln_add<<<rows, 256>>>(Q, TMP, lg + 5 * DM, lb + 5 * DM, Q);
    }

    // Final bilinear attention pooling (FIXED: per-batch stride = NS*DM, not NT).
    float* PQs = QKV;          // scratch: V * att_w
    float* Ts  = QKV + NT;     // scratch: att_maps @ Q
    vmul_k<<<(NTOK + 255) / 256, 256>>>(V, att_w, PQs, NTOK);
    mma_nt<<<dim3(NS / 64, NS / 128, BB), 256>>>(
        PQs, Q, SC, DM, DM, DM, NS,
        1, SBATCH, 0, SBATCH, 0, (long long)NS * NS, 0, 1.0f);
    softmax_final<<<BB * NS, 256>>>(SC, v_mask, q_mask, att_b);
    mma_nn<<<dim3(DM / 64, NS / 128, BB), 256>>>(
        SC, Q, (const float*)nullptr, Ts, NS, NS, DM, DM,
        1, (long long)NS * NS, 0, SBATCH, 0, SBATCH, 0, 0, 0);
    final_out_k<<<BB, 512>>>(V, Ts, (float*)d_out);
}

// round 8
// speedup vs baseline: 2.8300x; 1.3765x over previous
#include <cuda_runtime.h>
#include <cuda_bf16.h>
#include <cstdint>

// ---------------------------------------------------------------------------
// CoAttention R7 (=R4 + compile fix): tf32 mma + ldmatrix fragment loads.
// B=8, NV=NQ=512, D=512, H=8, dh=64, DF=2048, L=4
// ---------------------------------------------------------------------------

#define BB    8
#define NS    512
#define DM    512
#define NHEAD 8
#define DHH   64
#define DFF   2048
#define NLAY  4
#define LN_EPS 1e-5f

// ------------------------------- scratch -----------------------------------
__device__ float g_v  [BB*NS*DM];
__device__ float g_q  [BB*NS*DM];
__device__ float g_qkv[3*BB*NS*DM];
__device__ float g_sc [BB*NHEAD*NS*NS];
__device__ float g_ao [BB*NS*DM];
__device__ float g_tmp[BB*NS*DM];
__device__ float g_va [BB*NS*DM];
__device__ float g_qa [BB*NS*DM];
__device__ float g_vq [BB*NS*DM];
__device__ float g_qv [BB*NS*DM];
__device__ float g_ffn[BB*NS*DFF];

// ------------------------------- helpers -----------------------------------

__device__ __forceinline__ float to_tf32(float x) {
    unsigned u;
    asm("cvt.rna.tf32.f32 %0, %1;" : "=r"(u) : "f"(x));
    return __uint_as_float(u);
}

__device__ __forceinline__ void mma1688(float* c, const unsigned* a, const unsigned* b) {
    asm volatile(
        "mma.sync.aligned.m16n8k8.row.col.f32.tf32.tf32.f32 "
        "{%0,%1,%2,%3}, {%4,%5,%6,%7}, {%8,%9}, {%0,%1,%2,%3};\n"
        : "+f"(c[0]), "+f"(c[1]), "+f"(c[2]), "+f"(c[3])
        : "r"(a[0]), "r"(a[1]), "r"(a[2]), "r"(a[3]), "r"(b[0]), "r"(b[1]));
}

#define LDSM4(r0, r1, r2, r3, addr) \
    asm volatile("ldmatrix.sync.aligned.m8n8.x4.shared.b16 {%0,%1,%2,%3}, [%4];" \
        : "=r"(r0), "=r"(r1), "=r"(r2), "=r"(r3) : "r"(addr))

// smem strides (floats); 20 => conflict-free ldmatrix + 16B-aligned float4 STS
#define SSTR 20
#define ABUF_BYTES (128 * SSTR * 4)
#define BBUF_BYTES (64  * SSTR * 4)

// ------------------------------- kernels -----------------------------------

__global__ void copy_k(const float* __restrict__ src, float* __restrict__ dst, int n) {
    int i = blockIdx.x * blockDim.x + threadIdx.x;
    if (i < n) dst[i] = src[i];
}

// NN GEMM: C[M,N] = A[M,K] @ B[K,N] (+bias)(+relu). tf32 + ldmatrix.
// Block 128x64, BK=16, 256 thr = 8 warps (4x2), warp tile 32x32.
__global__ __launch_bounds__(256) void mma_nn(
    const float* __restrict__ A, const float* __restrict__ B,
    const float* __restrict__ bias, float* __restrict__ C,
    int K, int lda, int ldb, int ldc,
    int zdiv, long long sA1, long long sA2, long long sB1, long long sB2,
    long long sC1, long long sC2, long long sBias, int relu)
{
    int z = blockIdx.z;
    int z1 = z / zdiv, z2 = z - z1 * zdiv;
    A += z1 * sA1 + (long long)z2 * sA2;
    B += z1 * sB1 + (long long)z2 * sB2;
    C += z1 * sC1 + (long long)z2 * sC2;
    if (bias) bias += (long long)z * sBias;

    __shared__ float As[2][128][SSTR];   // [m][k]
    __shared__ float Bs[2][64][SSTR];    // [n][k]

    const int tid = threadIdx.x;
    const int wid = tid >> 5, lane = tid & 31;
    const int wm = (wid >> 1) * 32, wn = (wid & 1) * 32;
    const int g = lane >> 2, t4 = lane & 3;
    const int row0 = blockIdx.y * 128, col0 = blockIdx.x * 64;

    // A loader: float4 along k, 2 rows per thread
    const int am = tid >> 2, ak = (tid & 3) * 4;
    const float* Aptr  = A + (long long)(row0 + am) * lda + ak;
    const float* Aptr2 = Aptr + 64ll * lda;

    // B loader: transpose [k][n] -> [n][k]; 4 coalesced LDG + 1 STS.128
    const int bn = tid & 63, bkq = (tid >> 6) * 4;
    const float* Bptr = B + col0 + bn;

    // ldmatrix lane addressing
    const int lr = lane & 7, sel = lane >> 3;
    unsigned as0 = (unsigned)__cvta_generic_to_shared(&As[0][0][0]);
    unsigned bs0 = (unsigned)__cvta_generic_to_shared(&Bs[0][0][0]);
    unsigned aaddr0 = as0 + (unsigned)(((wm + (sel & 1) * 8 + lr) * SSTR + (sel >> 1) * 4) << 2);
    unsigned aaddr1 = aaddr0 + 16u * SSTR * 4u;
    unsigned baddr0 = bs0 + (unsigned)(((wn + (sel >> 1) * 8 + lr) * SSTR + (sel & 1) * 4) << 2);
    unsigned baddr1 = baddr0 + 16u * SSTR * 4u;

    float acc[2][4][4];
    #pragma unroll
    for (int mi = 0; mi < 2; mi++)
        #pragma unroll
        for (int ni = 0; ni < 4; ni++)
            #pragma unroll
            for (int r = 0; r < 4; r++) acc[mi][ni][r] = 0.f;

    // preload tile 0
    {
        float4 a0 = *(const float4*)(Aptr);
        float4 a1 = *(const float4*)(Aptr2);
        float4 ta, tb;
        ta.x = to_tf32(a0.x); ta.y = to_tf32(a0.y); ta.z = to_tf32(a0.z); ta.w = to_tf32(a0.w);
        tb.x = to_tf32(a1.x); tb.y = to_tf32(a1.y); tb.z = to_tf32(a1.z); tb.w = to_tf32(a1.w);
        *(float4*)(&As[0][am][ak])      = ta;
        *(float4*)(&As[0][am + 64][ak]) = tb;
        float4 bv;
        bv.x = to_tf32(Bptr[(long long)(bkq + 0) * ldb]);
        bv.y = to_tf32(Bptr[(long long)(bkq + 1) * ldb]);
        bv.z = to_tf32(Bptr[(long long)(bkq + 2) * ldb]);
        bv.w = to_tf32(Bptr[(long long)(bkq + 3) * ldb]);
        *(float4*)(&Bs[0][bn][bkq]) = bv;
    }
    __syncthreads();

    const int nk = K >> 4;
    for (int t = 0; t < nk; t++) {
        const int buf = t & 1;
        float4 ra, ra2; float rb[4];
        if (t + 1 < nk) {
            int k0 = (t + 1) << 4;
            ra  = *(const float4*)(Aptr + k0);
            ra2 = *(const float4*)(Aptr2 + k0);
            #pragma unroll
            for (int j = 0; j < 4; j++)
                rb[j] = Bptr[(long long)(k0 + bkq + j) * ldb];
        }

        #pragma unroll
        for (int ks = 0; ks < 2; ks++) {
            unsigned ao = (unsigned)(buf * ABUF_BYTES + ks * 32);
            unsigned bo = (unsigned)(buf * BBUF_BYTES + ks * 32);
            unsigned af0[4], af1[4], bf0[4], bf1[4];
            LDSM4(af0[0], af0[1], af0[2], af0[3], aaddr0 + ao);
            LDSM4(af1[0], af1[1], af1[2], af1[3], aaddr1 + ao);
            LDSM4(bf0[0], bf0[1], bf0[2], bf0[3], baddr0 + bo);
            LDSM4(bf1[0], bf1[1], bf1[2], bf1[3], baddr1 + bo);
            mma1688(acc[0][0], af0, &bf0[0]);
            mma1688(acc[0][1], af0, &bf0[2]);
            mma1688(acc[0][2], af0, &bf1[0]);
            mma1688(acc[0][3], af0, &bf1[2]);
            mma1688(acc[1][0], af1, &bf0[0]);
            mma1688(acc[1][1], af1, &bf0[2]);
            mma1688(acc[1][2], af1, &bf1[0]);
            mma1688(acc[1][3], af1, &bf1[2]);
        }

        if (t + 1 < nk) {
            const int nb = (t + 1) & 1;
            float4 ta, tb, bv;
            ta.x = to_tf32(ra.x);  ta.y = to_tf32(ra.y);  ta.z = to_tf32(ra.z);  ta.w = to_tf32(ra.w);
            tb.x = to_tf32(ra2.x); tb.y = to_tf32(ra2.y); tb.z = to_tf32(ra2.z); tb.w = to_tf32(ra2.w);
            bv.x = to_tf32(rb[0]); bv.y = to_tf32(rb[1]); bv.z = to_tf32(rb[2]); bv.w = to_tf32(rb[3]);
            *(float4*)(&As[nb][am][ak])      = ta;
            *(float4*)(&As[nb][am + 64][ak]) = tb;
            *(float4*)(&Bs[nb][bn][bkq])     = bv;
            __syncthreads();
        }
    }

    #pragma unroll
    for (int mi = 0; mi < 2; mi++)
        #pragma unroll
        for (int ni = 0; ni < 4; ni++) {
            int r = row0 + wm + mi * 16 + g;
            int c = col0 + wn + ni * 8 + 2 * t4;
            float b0v = 0.f, b1v = 0.f;
            if (bias) { b0v = bias[c]; b1v = bias[c + 1]; }
            float o0 = acc[mi][ni][0] + b0v;
            float o1 = acc[mi][ni][1] + b1v;
            float o2 = acc[mi][ni][2] + b0v;
            float o3 = acc[mi][ni][3] + b1v;
            if (relu) {
                o0 = fmaxf(o0, 0.f); o1 = fmaxf(o1, 0.f);
                o2 = fmaxf(o2, 0.f); o3 = fmaxf(o3, 0.f);
            }
            *(float2*)(C + (long long)r * ldc + c)       = make_float2(o0, o1);
            *(float2*)(C + (long long)(r + 8) * ldc + c) = make_float2(o2, o3);
        }
}

// NT GEMM: C[M,N] = scale * A[M,K] @ B[N,K]^T. tf32 + ldmatrix.
__global__ __launch_bounds__(256) void mma_nt(
    const float* __restrict__ A, const float* __restrict__ B,
    float* __restrict__ C,
    int K, int lda, int ldb, int ldc,
    int zdiv, long long sA1, long long sA2, long long sB1, long long sB2,
    long long sC1, long long sC2, float scale)
{
    int z = blockIdx.z;
    int z1 = z / zdiv, z2 = z - z1 * zdiv;
    A += z1 * sA1 + (long long)z2 * sA2;
    B += z1 * sB1 + (long long)z2 * sB2;
    C += z1 * sC1 + (long long)z2 * sC2;

    __shared__ float As[2][128][SSTR];
    __shared__ float Bs[2][64][SSTR];

    const int tid = threadIdx.x;
    const int wid = tid >> 5, lane = tid & 31;
    const int wm = (wid >> 1) * 32, wn = (wid & 1) * 32;
    const int g = lane >> 2, t4 = lane & 3;
    const int row0 = blockIdx.y * 128, col0 = blockIdx.x * 64;

    const int am = tid >> 2, ak = (tid & 3) * 4;
    const float* Aptr  = A + (long long)(row0 + am) * lda + ak;
    const float* Aptr2 = Aptr + 64ll * lda;

    const int bnr = tid >> 2, bk4 = (tid & 3) * 4;
    const float* Bptr = B + (long long)(col0 + bnr) * ldb + bk4;

    const int lr = lane & 7, sel = lane >> 3;
    unsigned as0 = (unsigned)__cvta_generic_to_shared(&As[0][0][0]);
    unsigned bs0 = (unsigned)__cvta_generic_to_shared(&Bs[0][0][0]);
    unsigned aaddr0 = as0 + (unsigned)(((wm + (sel & 1) * 8 + lr) * SSTR + (sel >> 1) * 4) << 2);
    unsigned aaddr1 = aaddr0 + 16u * SSTR * 4u;
    unsigned baddr0 = bs0 + (unsigned)(((wn + (sel >> 1) * 8 + lr) * SSTR + (sel & 1) * 4) << 2);
    unsigned baddr1 = baddr0 + 16u * SSTR * 4u;

    float acc[2][4][4];
    #pragma unroll
    for (int mi = 0; mi < 2; mi++)
        #pragma unroll
        for (int ni = 0; ni < 4; ni++)
            #pragma unroll
            for (int r = 0; r < 4; r++) acc[mi][ni][r] = 0.f;

    {
        float4 a0 = *(const float4*)(Aptr);
        float4 a1 = *(const float4*)(Aptr2);
        float4 b0 = *(const float4*)(Bptr);
        float4 ta, tb, bv;
        ta.x = to_tf32(a0.x); ta.y = to_tf32(a0.y); ta.z = to_tf32(a0.z); ta.w = to_tf32(a0.w);
        tb.x = to_tf32(a1.x); tb.y = to_tf32(a1.y); tb.z = to_tf32(a1.z); tb.w = to_tf32(a1.w);
        bv.x = to_tf32(b0.x); bv.y = to_tf32(b0.y); bv.z = to_tf32(b0.z); bv.w = to_tf32(b0.w);
        *(float4*)(&As[0][am][ak])      = ta;
        *(float4*)(&As[0][am + 64][ak]) = tb;
        *(float4*)(&Bs[0][bnr][bk4])    = bv;
    }
    __syncthreads();

    const int nk = K >> 4;
    for (int t = 0; t < nk; t++) {
        const int buf = t & 1;
        float4 ra, ra2, rb;
        if (t + 1 < nk) {
            int k0 = (t + 1) << 4;
            ra  = *(const float4*)(Aptr + k0);
            ra2 = *(const float4*)(Aptr2 + k0);
            rb  = *(const float4*)(Bptr + k0);
        }

        #pragma unroll
        for (int ks = 0; ks < 2; ks++) {
            unsigned ao = (unsigned)(buf * ABUF_BYTES + ks * 32);
            unsigned bo = (unsigned)(buf * BBUF_BYTES + ks * 32);
            unsigned af0[4], af1[4], bf0[4], bf1[4];
            LDSM4(af0[0], af0[1], af0[2], af0[3], aaddr0 + ao);
            LDSM4(af1[0], af1[1], af1[2], af1[3], aaddr1 + ao);
            LDSM4(bf0[0], bf0[1], bf0[2], bf0[3], baddr0 + bo);
            LDSM4(bf1[0], bf1[1], bf1[2], bf1[3], baddr1 + bo);
            mma1688(acc[0][0], af0, &bf0[0]);
            mma1688(acc[0][1], af0, &bf0[2]);
            mma1688(acc[0][2], af0, &bf1[0]);
            mma1688(acc[0][3], af0, &bf1[2]);
            mma1688(acc[1][0], af1, &bf0[0]);
            mma1688(acc[1][1], af1, &bf0[2]);
            mma1688(acc[1][2], af1, &bf1[0]);
            mma1688(acc[1][3], af1, &bf1[2]);
        }

        if (t + 1 < nk) {
            const int nb = (t + 1) & 1;
            float4 ta, tb, bv;
            ta.x = to_tf32(ra.x);  ta.y = to_tf32(ra.y);  ta.z = to_tf32(ra.z);  ta.w = to_tf32(ra.w);
            tb.x = to_tf32(ra2.x); tb.y = to_tf32(ra2.y); tb.z = to_tf32(ra2.z); tb.w = to_tf32(ra2.w);
            bv.x = to_tf32(rb.x);  bv.y = to_tf32(rb.y);  bv.z = to_tf32(rb.z);  bv.w = to_tf32(rb.w);
            *(float4*)(&As[nb][am][ak])      = ta;
            *(float4*)(&As[nb][am + 64][ak]) = tb;
            *(float4*)(&Bs[nb][bnr][bk4])    = bv;
            __syncthreads();
        }
    }

    #pragma unroll
    for (int mi = 0; mi < 2; mi++)
        #pragma unroll
        for (int ni = 0; ni < 4; ni++) {
            int r = row0 + wm + mi * 16 + g;
            int c = col0 + wn + ni * 8 + 2 * t4;
            *(float2*)(C + (long long)r * ldc + c) =
                make_float2(acc[mi][ni][0] * scale, acc[mi][ni][1] * scale);
            *(float2*)(C + (long long)(r + 8) * ldc + c) =
                make_float2(acc[mi][ni][2] * scale, acc[mi][ni][3] * scale);
        }
}

// Row softmax with key-padding mask. rows = B*H*N, len = N.
__global__ __launch_bounds__(256) void softmax_attn(
    float* __restrict__ S, const int* __restrict__ mask)
{
    int row = blockIdx.x;
    int b = row >> 12;
    float* Sp = S + (long long)row * NS;
    const int* mp = mask + b * NS;
    int tid = threadIdx.x;

    float v0 = mp[tid]       ? Sp[tid]       : -1e9f;
    float v1 = mp[tid + 256] ? Sp[tid + 256] : -1e9f;

    __shared__ float red[256];
    red[tid] = fmaxf(v0, v1);
    __syncthreads();
    for (int s = 128; s > 0; s >>= 1) {
        if (tid < s) red[tid] = fmaxf(red[tid], red[tid + s]);
        __syncthreads();
    }
    float m = red[0];
    __syncthreads();

    float e0 = __expf(v0 - m), e1 = __expf(v1 - m);
    red[tid] = e0 + e1;
    __syncthreads();
    for (int s = 128; s > 0; s >>= 1) {
        if (tid < s) red[tid] += red[tid + s];
        __syncthreads();
    }
    float inv = 1.f / red[0];
    Sp[tid]       = e0 * inv;
    Sp[tid + 256] = e1 * inv;
}

// out[row] = LN(x[row] + y[row]) * g + b.
__global__ __launch_bounds__(256) void ln_add(
    const float* __restrict__ X, const float* __restrict__ Y,
    const float* __restrict__ g, const float* __restrict__ be,
    float* __restrict__ O)
{
    int row = blockIdx.x;
    const float* xp = X + (long long)row * DM;
    const float* yp = Y + (long long)row * DM;
    float* op = O + (long long)row * DM;
    int tid = threadIdx.x;

    float a0 = xp[tid] + yp[tid];
    float a1 = xp[tid + 256] + yp[tid + 256];

    __shared__ float r1[256];
    __shared__ float r2[256];
    r1[tid] = a0 + a1;
    r2[tid] = a0 * a0 + a1 * a1;
    __syncthreads();
    for (int s = 128; s > 0; s >>= 1) {
        if (tid < s) { r1[tid] += r1[tid + s]; r2[tid] += r2[tid + s]; }
        __syncthreads();
    }
    float mean = r1[0] * (1.f / DM);
    float var  = r2[0] * (1.f / DM) - mean * mean;
    float rstd = rsqrtf(var + LN_EPS);
    op[tid]       = (a0 - mean) * rstd * g[tid]       + be[tid];
    op[tid + 256] = (a1 - mean) * rstd * g[tid + 256] + be[tid + 256];
}

__global__ void vmul_k(const float* __restrict__ v, const float* __restrict__ w,
                       float* __restrict__ o, int n) {
    int i = blockIdx.x * blockDim.x + threadIdx.x;
    if (i < n) o[i] = v[i] * w[i & (DM - 1)];
}

__global__ __launch_bounds__(256) void softmax_final(
    float* __restrict__ S, const int* __restrict__ vmask,
    const int* __restrict__ qmask, const float* __restrict__ attb)
{
    int row = blockIdx.x;
    int b = row >> 9, i = row & (NS - 1);
    int rowpad = (vmask[b * NS + i] == 0);
    float ab = attb[0];
    float* Sp = S + (long long)row * NS;
    int tid = threadIdx.x;

    float v0 = (rowpad || qmask[b * NS + tid] == 0)       ? -1e9f : Sp[tid] + ab;
    float v1 = (rowpad || qmask[b * NS + tid + 256] == 0) ? -1e9f : Sp[tid + 256] + ab;

    __shared__ float red[256];
    red[tid] = fmaxf(v0, v1);
    __syncthreads();
    for (int s = 128; s > 0; s >>= 1) {
        if (tid < s) red[tid] = fmaxf(red[tid], red[tid + s]);
        __syncthreads();
    }
    float m = red[0];
    __syncthreads();

    float e0 = __expf(v0 - m), e1 = __expf(v1 - m);
    red[tid] = e0 + e1;
    __syncthreads();
    for (int s = 128; s > 0; s >>= 1) {
        if (tid < s) red[tid] += red[tid + s];
        __syncthreads();
    }
    float inv = 1.f / red[0];
    Sp[tid]       = e0 * inv;
    Sp[tid + 256] = e1 * inv;
}

__global__ void final_out_k(const float* __restrict__ V, const float* __restrict__ T,
                            float* __restrict__ out) {
    int b = blockIdx.x;
    int k = threadIdx.x;
    const float* vp = V + (long long)b * NS * DM;
    const float* tp = T + (long long)b * NS * DM;
    float acc = 0.f;
    #pragma unroll 4
    for (int i = 0; i < NS; i++)
        acc = fmaf(vp[(long long)i * DM + k], tp[(long long)i * DM + k], acc);
    out[b * DM + k] = acc * (1.f / 512.f);
}

// ------------------------------- host side ---------------------------------

static void run_mha(const float* xq, const float* xkv, const int* mask,
                    const float* w, const float* b,
                    const float* wo, const float* bo,
                    float* QKV, float* SC, float* AO, float* out)
{
    const long long NT = (long long)BB * NS * DM;
    const long long WSTRIDE = (long long)DM * DM;

    mma_nn<<<dim3(DM / 64, (BB * NS) / 128, 1), 256>>>(
        xq, w, b, QKV, DM, DM, DM, DM,
        1, 0, 0, 0, 0, 0, 0, DM, 0);
    mma_nn<<<dim3(DM / 64, (BB * NS) / 128, 2), 256>>>(
        xkv, w + WSTRIDE, b + DM, QKV + NT, DM, DM, DM, DM,
        1, 0, 0, WSTRIDE, 0, NT, 0, DM, 0);

    const float* PQ = QKV;
    const float* PK = QKV + NT;
    const float* PV = QKV + 2 * NT;

    mma_nt<<<dim3(NS / 64, NS / 128, BB * NHEAD), 256>>>(
        PQ, PK, SC, DHH, DM, DM, NS,
        NHEAD, (long long)NS * DM, DHH, (long long)NS * DM, DHH,
        (long long)NHEAD * NS * NS, (long long)NS * NS, 0.125f);

    softmax_attn<<<BB * NHEAD * NS, 256>>>(SC, mask);

    mma_nn<<<dim3(1, NS / 128, BB * NHEAD), 256>>>(
        SC, PV, (const float*)nullptr, AO, NS, NS, DM, DM,
        NHEAD, (long long)NHEAD * NS * NS, (long long)NS * NS,
        (long long)NS * DM, DHH,
        (long long)NS * DM, DHH, 0, 0);

    mma_nn<<<dim3(DM / 64, (BB * NS) / 128, 1), 256>>>(
        AO, wo, bo, out, DM, DM, DM, DM,
        1, 0, 0, 0, 0, 0, 0, DM, 0);
}

extern "C" void kernel_launch(void* const* d_in, const int* in_sizes, int n_in,
                              void* d_out, int out_size)
{
    const float *v_in, *q_in, *attn_w, *attn_b, *attn_wo, *attn_bo;
    const float *ln_g, *ln_b, *fw1, *fb1, *fw2, *fb2, *att_w, *att_b;
    const int *v_mask, *q_mask;

    if (in_sizes[2] == BB * NS) {   // dict order
        v_in    = (const float*)d_in[0];
        q_in    = (const float*)d_in[1];
        v_mask  = (const int*)  d_in[2];
        q_mask  = (const int*)  d_in[3];
        attn_w  = (const float*)d_in[4];
        attn_b  = (const float*)d_in[5];
        attn_wo = (const float*)d_in[6];
        attn_bo = (const float*)d_in[7];
        ln_g    = (const float*)d_in[8];
        ln_b    = (const float*)d_in[9];
        fw1     = (const float*)d_in[10];
        fb1     = (const float*)d_in[11];
        fw2     = (const float*)d_in[12];
        fb2     = (const float*)d_in[13];
        att_w   = (const float*)d_in[14];
        att_b   = (const float*)d_in[15];
    } else {                        // signature order
        v_in    = (const float*)d_in[0];
        q_in    = (const float*)d_in[1];
        attn_w  = (const float*)d_in[2];
        attn_b  = (const float*)d_in[3];
        attn_wo = (const float*)d_in[4];
        attn_bo = (const float*)d_in[5];
        ln_g    = (const float*)d_in[6];
        ln_b    = (const float*)d_in[7];
        fw1     = (const float*)d_in[8];
        fb1     = (const float*)d_in[9];
        fw2     = (const float*)d_in[10];
        fb2     = (const float*)d_in[11];
        att_w   = (const float*)d_in[12];
        att_b   = (const float*)d_in[13];
        v_mask  = (const int*)  d_in[14];
        q_mask  = (const int*)  d_in[15];
    }

    float *V, *Q, *QKV, *SC, *AO, *TMP, *VA, *QA, *VQ, *QV, *FFN;
    cudaGetSymbolAddress((void**)&V,   g_v);
    cudaGetSymbolAddress((void**)&Q,   g_q);
    cudaGetSymbolAddress((void**)&QKV, g_qkv);
    cudaGetSymbolAddress((void**)&SC,  g_sc);
    cudaGetSymbolAddress((void**)&AO,  g_ao);
    cudaGetSymbolAddress((void**)&TMP, g_tmp);
    cudaGetSymbolAddress((void**)&VA,  g_va);
    cudaGetSymbolAddress((void**)&QA,  g_qa);
    cudaGetSymbolAddress((void**)&VQ,  g_vq);
    cudaGetSymbolAddress((void**)&QV,  g_qv);
    cudaGetSymbolAddress((void**)&FFN, g_ffn);

    const int NTOK = BB * NS * DM;
    const long long NT = (long long)NTOK;
    const long long SBATCH = (long long)NS * DM;
    copy_k<<<(NTOK + 255) / 256, 256>>>(v_in, V, NTOK);
    copy_k<<<(NTOK + 255) / 256, 256>>>(q_in, Q, NTOK);

    const int rows = BB * NS;

    for (int i = 0; i < NLAY; i++) {
        const float* aw  = attn_w  + (long long)i * 4 * 3 * DM * DM;
        const float* ab  = attn_b  + (long long)i * 4 * 3 * DM;
        const float* awo = attn_wo + (long long)i * 4 * DM * DM;
        const float* abo = attn_bo + (long long)i * 4 * DM;
        const float* lg  = ln_g + (long long)i * 6 * DM;
        const float* lb  = ln_b + (long long)i * 6 * DM;

        run_mha(V, V, v_mask, aw, ab, awo, abo, QKV, SC, AO, TMP);
        ln_add<<<rows, 256>>>(V, TMP, lg, lb, VA);

        run_mha(Q, Q, q_mask,
                aw + 3ll * DM * DM, ab + 3 * DM, awo + (long long)DM * DM, abo + DM,
                QKV, SC, AO, TMP);
        ln_add<<<rows, 256>>>(Q, TMP, lg + DM, lb + DM, QA);

        run_mha(VA, QA, q_mask,
                aw + 6ll * DM * DM, ab + 6 * DM, awo + 2ll * DM * DM, abo + 2 * DM,
                QKV, SC, AO, VQ);
        run_mha(QA, VQ, v_mask,
                aw + 9ll * DM * DM, ab + 9 * DM, awo + 3ll * DM * DM, abo + 3 * DM,
                QKV, SC, AO, QV);

        ln_add<<<rows, 256>>>(V, VQ, lg + 2 * DM, lb + 2 * DM, V);
        ln_add<<<rows, 256>>>(Q, QV, lg + 3 * DM, lb + 3 * DM, Q);

        const float* w1v = fw1 + (long long)i * 2 * DM * DFF;
        const float* b1v = fb1 + (long long)i * 2 * DFF;
        const float* w2v = fw2 + (long long)i * 2 * DFF * DM;
        const float* b2v = fb2 + (long long)i * 2 * DM;

        mma_nn<<<dim3(DFF / 64, rows / 128, 1), 256>>>(
            V, w1v, b1v, FFN, DM, DM, DFF, DFF,
            1, 0, 0, 0, 0, 0, 0, 0, 1);
        mma_nn<<<dim3(DM / 64, rows / 128, 1), 256>>>(
            FFN, w2v, b2v, TMP, DFF, DFF, DM, DM,
            1, 0, 0, 0, 0, 0, 0, 0, 0);
        ln_add<<<rows, 256>>>(V, TMP, lg + 4 * DM, lb + 4 * DM, V);

        mma_nn<<<dim3(DFF / 64, rows / 128, 1), 256>>>(
            Q, w1v + (long long)DM * DFF, b1v + DFF, FFN, DM, DM, DFF, DFF,
            1, 0, 0, 0, 0, 0, 0, 0, 1);
        mma_nn<<<dim3(DM / 64, rows / 128, 1), 256>>>(
            FFN, w2v + (long long)DFF * DM, b2v + DM, TMP, DFF, DFF, DM, DM,
            1, 0, 0, 0, 0, 0, 0, 0, 0);
        ln_add<<<rows, 256>>>(Q, TMP, lg + 5 * DM, lb + 5 * DM, Q);
    }

    // Final bilinear attention pooling.
    float* PQs = QKV;
    float* Ts  = QKV + NT;
    vmul_k<<<(NTOK + 255) / 256, 256>>>(V, att_w, PQs, NTOK);
    mma_nt<<<dim3(NS / 64, NS / 128, BB), 256>>>(
        PQs, Q, SC, DM, DM, DM, NS,
        1, SBATCH, 0, SBATCH, 0, (long long)NS * NS, 0, 1.0f);
    softmax_final<<<BB * NS, 256>>>(SC, v_mask, q_mask, att_b);
    mma_nn<<<dim3(DM / 64, NS / 128, BB), 256>>>(
        SC, Q, (const float*)nullptr, Ts, NS, NS, DM, DM,
        1, (long long)NS * NS, 0, SBATCH, 0, SBATCH, 0, 0, 0);
    final_out_k<<<BB, 512>>>(V, Ts, (float*)d_out);
}

// round 9
// speedup vs baseline: 2.8701x; 1.0142x over previous
#include <cuda_runtime.h>
#include <cuda_bf16.h>
#include <cstdint>

// ---------------------------------------------------------------------------
// CoAttention R8: wider warp tile (32x64) => 16 MMA per 6 ldmatrix.
// Main GEMMs: block 64x128, 128 threads. AV GEMM keeps 128x64 kernel.
// ---------------------------------------------------------------------------

#define BB    8
#define NS    512
#define DM    512
#define NHEAD 8
#define DHH   64
#define DFF   2048
#define NLAY  4
#define LN_EPS 1e-5f

// ------------------------------- scratch -----------------------------------
__device__ float g_v  [BB*NS*DM];
__device__ float g_q  [BB*NS*DM];
__device__ float g_qkv[3*BB*NS*DM];
__device__ float g_sc [BB*NHEAD*NS*NS];
__device__ float g_ao [BB*NS*DM];
__device__ float g_tmp[BB*NS*DM];
__device__ float g_va [BB*NS*DM];
__device__ float g_qa [BB*NS*DM];
__device__ float g_vq [BB*NS*DM];
__device__ float g_qv [BB*NS*DM];
__device__ float g_ffn[BB*NS*DFF];

// ------------------------------- helpers -----------------------------------

__device__ __forceinline__ float to_tf32(float x) {
    unsigned u;
    asm("cvt.rna.tf32.f32 %0, %1;" : "=r"(u) : "f"(x));
    return __uint_as_float(u);
}

__device__ __forceinline__ void mma1688(float* c, const unsigned* a, const unsigned* b) {
    asm volatile(
        "mma.sync.aligned.m16n8k8.row.col.f32.tf32.tf32.f32 "
        "{%0,%1,%2,%3}, {%4,%5,%6,%7}, {%8,%9}, {%0,%1,%2,%3};\n"
        : "+f"(c[0]), "+f"(c[1]), "+f"(c[2]), "+f"(c[3])
        : "r"(a[0]), "r"(a[1]), "r"(a[2]), "r"(a[3]), "r"(b[0]), "r"(b[1]));
}

#define LDSM4(r0, r1, r2, r3, addr) \
    asm volatile("ldmatrix.sync.aligned.m8n8.x4.shared.b16 {%0,%1,%2,%3}, [%4];" \
        : "=r"(r0), "=r"(r1), "=r"(r2), "=r"(r3) : "r"(addr))

#define SSTR 20
// big-kernel (64x128) buffers
#define A2BUF (64  * SSTR * 4)
#define B2BUF (128 * SSTR * 4)
// AV-kernel (128x64) buffers
#define ABUF_BYTES (128 * SSTR * 4)
#define BBUF_BYTES (64  * SSTR * 4)

// ------------------------------- kernels -----------------------------------

__global__ void copy_k(const float* __restrict__ src, float* __restrict__ dst, int n) {
    int i = blockIdx.x * blockDim.x + threadIdx.x;
    if (i < n) dst[i] = src[i];
}

// ======== NN GEMM, block 64x128, BK=16, 128 thr = 4 warps of 32x64 =========
__global__ __launch_bounds__(128) void mma_nn2(
    const float* __restrict__ A, const float* __restrict__ B,
    const float* __restrict__ bias, float* __restrict__ C,
    int K, int lda, int ldb, int ldc,
    int zdiv, long long sA1, long long sA2, long long sB1, long long sB2,
    long long sC1, long long sC2, long long sBias, int relu)
{
    int z = blockIdx.z;
    int z1 = z / zdiv, z2 = z - z1 * zdiv;
    A += z1 * sA1 + (long long)z2 * sA2;
    B += z1 * sB1 + (long long)z2 * sB2;
    C += z1 * sC1 + (long long)z2 * sC2;
    if (bias) bias += (long long)z * sBias;

    __shared__ float As[2][64][SSTR];    // [m][k]
    __shared__ float Bs[2][128][SSTR];   // [n][k]

    const int tid = threadIdx.x;
    const int wid = tid >> 5, lane = tid & 31;
    const int wm = (wid >> 1) * 32, wn = (wid & 1) * 64;
    const int g = lane >> 2, t4 = lane & 3;
    const int row0 = blockIdx.y * 64, col0 = blockIdx.x * 128;

    // A loader: 2 float4 per thread (rows tid>>2 and +32)
    const int a_r = tid >> 2, a_k = (tid & 3) * 4;
    const float* Aptr  = A + (long long)(row0 + a_r) * lda + a_k;
    const float* Aptr2 = Aptr + 32ll * lda;

    // B loader (transpose [k][n]->[n][k]): thread owns column n=tid, 16 k rows
    const float* Bptr = B + col0 + tid;

    const int lr = lane & 7, sel = lane >> 3;
    unsigned as0 = (unsigned)__cvta_generic_to_shared(&As[0][0][0]);
    unsigned bs0 = (unsigned)__cvta_generic_to_shared(&Bs[0][0][0]);
    unsigned aaddr0 = as0 + (unsigned)(((wm + (sel & 1) * 8 + lr) * SSTR + (sel >> 1) * 4) << 2);
    unsigned aaddr1 = aaddr0 + 16u * SSTR * 4u;
    unsigned baddr[4];
    #pragma unroll
    for (int j = 0; j < 4; j++)
        baddr[j] = bs0 + (unsigned)(((wn + j * 16 + (sel >> 1) * 8 + lr) * SSTR + (sel & 1) * 4) << 2);

    float acc[2][8][4];
    #pragma unroll
    for (int mi = 0; mi < 2; mi++)
        #pragma unroll
        for (int ni = 0; ni < 8; ni++)
            #pragma unroll
            for (int r = 0; r < 4; r++) acc[mi][ni][r] = 0.f;

    // preload tile 0
    {
        float4 a0 = *(const float4*)(Aptr);
        float4 a1 = *(const float4*)(Aptr2);
        float4 ta, tb;
        ta.x = to_tf32(a0.x); ta.y = to_tf32(a0.y); ta.z = to_tf32(a0.z); ta.w = to_tf32(a0.w);
        tb.x = to_tf32(a1.x); tb.y = to_tf32(a1.y); tb.z = to_tf32(a1.z); tb.w = to_tf32(a1.w);
        *(float4*)(&As[0][a_r][a_k])      = ta;
        *(float4*)(&As[0][a_r + 32][a_k]) = tb;
        #pragma unroll
        for (int j = 0; j < 4; j++) {
            float4 bv;
            bv.x = to_tf32(Bptr[(long long)(j * 4 + 0) * ldb]);
            bv.y = to_tf32(Bptr[(long long)(j * 4 + 1) * ldb]);
            bv.z = to_tf32(Bptr[(long long)(j * 4 + 2) * ldb]);
            bv.w = to_tf32(Bptr[(long long)(j * 4 + 3) * ldb]);
            *(float4*)(&Bs[0][tid][j * 4]) = bv;
        }
    }
    __syncthreads();

    const int nk = K >> 4;
    for (int t = 0; t < nk; t++) {
        const int buf = t & 1;
        float4 ra, ra2; float rb[16];
        if (t + 1 < nk) {
            int k0 = (t + 1) << 4;
            ra  = *(const float4*)(Aptr + k0);
            ra2 = *(const float4*)(Aptr2 + k0);
            #pragma unroll
            for (int j = 0; j < 16; j++)
                rb[j] = Bptr[(long long)(k0 + j) * ldb];
        }

        #pragma unroll
        for (int ks = 0; ks < 2; ks++) {
            unsigned ao = (unsigned)(buf * A2BUF + ks * 32);
            unsigned bo = (unsigned)(buf * B2BUF + ks * 32);
            unsigned af0[4], af1[4], bf[4][4];
            LDSM4(af0[0], af0[1], af0[2], af0[3], aaddr0 + ao);
            LDSM4(af1[0], af1[1], af1[2], af1[3], aaddr1 + ao);
            #pragma unroll
            for (int j = 0; j < 4; j++)
                LDSM4(bf[j][0], bf[j][1], bf[j][2], bf[j][3], baddr[j] + bo);
            #pragma unroll
            for (int j = 0; j < 4; j++) {
                mma1688(acc[0][2 * j],     af0, &bf[j][0]);
                mma1688(acc[0][2 * j + 1], af0, &bf[j][2]);
                mma1688(acc[1][2 * j],     af1, &bf[j][0]);
                mma1688(acc[1][2 * j + 1], af1, &bf[j][2]);
            }
        }

        if (t + 1 < nk) {
            const int nb = (t + 1) & 1;
            float4 ta, tb;
            ta.x = to_tf32(ra.x);  ta.y = to_tf32(ra.y);  ta.z = to_tf32(ra.z);  ta.w = to_tf32(ra.w);
            tb.x = to_tf32(ra2.x); tb.y = to_tf32(ra2.y); tb.z = to_tf32(ra2.z); tb.w = to_tf32(ra2.w);
            *(float4*)(&As[nb][a_r][a_k])      = ta;
            *(float4*)(&As[nb][a_r + 32][a_k]) = tb;
            #pragma unroll
            for (int j = 0; j < 4; j++) {
                float4 bv;
                bv.x = to_tf32(rb[j * 4 + 0]);
                bv.y = to_tf32(rb[j * 4 + 1]);
                bv.z = to_tf32(rb[j * 4 + 2]);
                bv.w = to_tf32(rb[j * 4 + 3]);
                *(float4*)(&Bs[nb][tid][j * 4]) = bv;
            }
            __syncthreads();
        }
    }

    #pragma unroll
    for (int mi = 0; mi < 2; mi++)
        #pragma unroll
        for (int ni = 0; ni < 8; ni++) {
            int r = row0 + wm + mi * 16 + g;
            int c = col0 + wn + ni * 8 + 2 * t4;
            float b0v = 0.f, b1v = 0.f;
            if (bias) { b0v = bias[c]; b1v = bias[c + 1]; }
            float o0 = acc[mi][ni][0] + b0v;
            float o1 = acc[mi][ni][1] + b1v;
            float o2 = acc[mi][ni][2] + b0v;
            float o3 = acc[mi][ni][3] + b1v;
            if (relu) {
                o0 = fmaxf(o0, 0.f); o1 = fmaxf(o1, 0.f);
                o2 = fmaxf(o2, 0.f); o3 = fmaxf(o3, 0.f);
            }
            *(float2*)(C + (long long)r * ldc + c)       = make_float2(o0, o1);
            *(float2*)(C + (long long)(r + 8) * ldc + c) = make_float2(o2, o3);
        }
}

// ======== NT GEMM, block 64x128, BK=16, 128 thr = 4 warps of 32x64 =========
__global__ __launch_bounds__(128) void mma_nt2(
    const float* __restrict__ A, const float* __restrict__ B,
    float* __restrict__ C,
    int K, int lda, int ldb, int ldc,
    int zdiv, long long sA1, long long sA2, long long sB1, long long sB2,
    long long sC1, long long sC2, float scale)
{
    int z = blockIdx.z;
    int z1 = z / zdiv, z2 = z - z1 * zdiv;
    A += z1 * sA1 + (long long)z2 * sA2;
    B += z1 * sB1 + (long long)z2 * sB2;
    C += z1 * sC1 + (long long)z2 * sC2;

    __shared__ float As[2][64][SSTR];
    __shared__ float Bs[2][128][SSTR];

    const int tid = threadIdx.x;
    const int wid = tid >> 5, lane = tid & 31;
    const int wm = (wid >> 1) * 32, wn = (wid & 1) * 64;
    const int g = lane >> 2, t4 = lane & 3;
    const int row0 = blockIdx.y * 64, col0 = blockIdx.x * 128;

    const int a_r = tid >> 2, a_k = (tid & 3) * 4;
    const float* Aptr  = A + (long long)(row0 + a_r) * lda + a_k;
    const float* Aptr2 = Aptr + 32ll * lda;

    // B loader: row n = tid, 16 contiguous k
    const float* Bptr = B + (long long)(col0 + tid) * ldb;

    const int lr = lane & 7, sel = lane >> 3;
    unsigned as0 = (unsigned)__cvta_generic_to_shared(&As[0][0][0]);
    unsigned bs0 = (unsigned)__cvta_generic_to_shared(&Bs[0][0][0]);
    unsigned aaddr0 = as0 + (unsigned)(((wm + (sel & 1) * 8 + lr) * SSTR + (sel >> 1) * 4) << 2);
    unsigned aaddr1 = aaddr0 + 16u * SSTR * 4u;
    unsigned baddr[4];
    #pragma unroll
    for (int j = 0; j < 4; j++)
        baddr[j] = bs0 + (unsigned)(((wn + j * 16 + (sel >> 1) * 8 + lr) * SSTR + (sel & 1) * 4) << 2);

    float acc[2][8][4];
    #pragma unroll
    for (int mi = 0; mi < 2; mi++)
        #pragma unroll
        for (int ni = 0; ni < 8; ni++)
            #pragma unroll
            for (int r = 0; r < 4; r++) acc[mi][ni][r] = 0.f;

    {
        float4 a0 = *(const float4*)(Aptr);
        float4 a1 = *(const float4*)(Aptr2);
        float4 ta, tb;
        ta.x = to_tf32(a0.x); ta.y = to_tf32(a0.y); ta.z = to_tf32(a0.z); ta.w = to_tf32(a0.w);
        tb.x = to_tf32(a1.x); tb.y = to_tf32(a1.y); tb.z = to_tf32(a1.z); tb.w = to_tf32(a1.w);
        *(float4*)(&As[0][a_r][a_k])      = ta;
        *(float4*)(&As[0][a_r + 32][a_k]) = tb;
        #pragma unroll
        for (int j = 0; j < 4; j++) {
            float4 b0 = *(const float4*)(Bptr + j * 4);
            float4 bv;
            bv.x = to_tf32(b0.x); bv.y = to_tf32(b0.y);
            bv.z = to_tf32(b0.z); bv.w = to_tf32(b0.w);
            *(float4*)(&Bs[0][tid][j * 4]) = bv;
        }
    }
    __syncthreads();

    const int nk = K >> 4;
    for (int t = 0; t < nk; t++) {
        const int buf = t & 1;
        float4 ra, ra2, rb[4];
        if (t + 1 < nk) {
            int k0 = (t + 1) << 4;
            ra  = *(const float4*)(Aptr + k0);
            ra2 = *(const float4*)(Aptr2 + k0);
            #pragma unroll
            for (int j = 0; j < 4; j++)
                rb[j] = *(const float4*)(Bptr + k0 + j * 4);
        }

        #pragma unroll
        for (int ks = 0; ks < 2; ks++) {
            unsigned ao = (unsigned)(buf * A2BUF + ks * 32);
            unsigned bo = (unsigned)(buf * B2BUF + ks * 32);
            unsigned af0[4], af1[4], bf[4][4];
            LDSM4(af0[0], af0[1], af0[2], af0[3], aaddr0 + ao);
            LDSM4(af1[0], af1[1], af1[2], af1[3], aaddr1 + ao);
            #pragma unroll
            for (int j = 0; j < 4; j++)
                LDSM4(bf[j][0], bf[j][1], bf[j][2], bf[j][3], baddr[j] + bo);
            #pragma unroll
            for (int j = 0; j < 4; j++) {
                mma1688(acc[0][2 * j],     af0, &bf[j][0]);
                mma1688(acc[0][2 * j + 1], af0, &bf[j][2]);
                mma1688(acc[1][2 * j],     af1, &bf[j][0]);
                mma1688(acc[1][2 * j + 1], af1, &bf[j][2]);
            }
        }

        if (t + 1 < nk) {
            const int nb = (t + 1) & 1;
            float4 ta, tb;
            ta.x = to_tf32(ra.x);  ta.y = to_tf32(ra.y);  ta.z = to_tf32(ra.z);  ta.w = to_tf32(ra.w);
            tb.x = to_tf32(ra2.x); tb.y = to_tf32(ra2.y); tb.z = to_tf32(ra2.z); tb.w = to_tf32(ra2.w);
            *(float4*)(&As[nb][a_r][a_k])      = ta;
            *(float4*)(&As[nb][a_r + 32][a_k]) = tb;
            #pragma unroll
            for (int j = 0; j < 4; j++) {
                float4 bv;
                bv.x = to_tf32(rb[j].x); bv.y = to_tf32(rb[j].y);
                bv.z = to_tf32(rb[j].z); bv.w = to_tf32(rb[j].w);
                *(float4*)(&Bs[nb][tid][j * 4]) = bv;
            }
            __syncthreads();
        }
    }

    #pragma unroll
    for (int mi = 0; mi < 2; mi++)
        #pragma unroll
        for (int ni = 0; ni < 8; ni++) {
            int r = row0 + wm + mi * 16 + g;
            int c = col0 + wn + ni * 8 + 2 * t4;
            *(float2*)(C + (long long)r * ldc + c) =
                make_float2(acc[mi][ni][0] * scale, acc[mi][ni][1] * scale);
            *(float2*)(C + (long long)(r + 8) * ldc + c) =
                make_float2(acc[mi][ni][2] * scale, acc[mi][ni][3] * scale);
        }
}

// ======== AV GEMM (N=64): block 128x64, 256 thr, warp 32x32 (R7 kernel) ====
__global__ __launch_bounds__(256) void mma_nn(
    const float* __restrict__ A, const float* __restrict__ B,
    const float* __restrict__ bias, float* __restrict__ C,
    int K, int lda, int ldb, int ldc,
    int zdiv, long long sA1, long long sA2, long long sB1, long long sB2,
    long long sC1, long long sC2, long long sBias, int relu)
{
    int z = blockIdx.z;
    int z1 = z / zdiv, z2 = z - z1 * zdiv;
    A += z1 * sA1 + (long long)z2 * sA2;
    B += z1 * sB1 + (long long)z2 * sB2;
    C += z1 * sC1 + (long long)z2 * sC2;
    if (bias) bias += (long long)z * sBias;

    __shared__ float As[2][128][SSTR];
    __shared__ float Bs[2][64][SSTR];

    const int tid = threadIdx.x;
    const int wid = tid >> 5, lane = tid & 31;
    const int wm = (wid >> 1) * 32, wn = (wid & 1) * 32;
    const int g = lane >> 2, t4 = lane & 3;
    const int row0 = blockIdx.y * 128, col0 = blockIdx.x * 64;

    const int am = tid >> 2, ak = (tid & 3) * 4;
    const float* Aptr  = A + (long long)(row0 + am) * lda + ak;
    const float* Aptr2 = Aptr + 64ll * lda;

    const int bn = tid & 63, bkq = (tid >> 6) * 4;
    const float* Bptr = B + col0 + bn;

    const int lr = lane & 7, sel = lane >> 3;
    unsigned as0 = (unsigned)__cvta_generic_to_shared(&As[0][0][0]);
    unsigned bs0 = (unsigned)__cvta_generic_to_shared(&Bs[0][0][0]);
    unsigned aaddr0 = as0 + (unsigned)(((wm + (sel & 1) * 8 + lr) * SSTR + (sel >> 1) * 4) << 2);
    unsigned aaddr1 = aaddr0 + 16u * SSTR * 4u;
    unsigned baddr0 = bs0 + (unsigned)(((wn + (sel >> 1) * 8 + lr) * SSTR + (sel & 1) * 4) << 2);
    unsigned baddr1 = baddr0 + 16u * SSTR * 4u;

    float acc[2][4][4];
    #pragma unroll
    for (int mi = 0; mi < 2; mi++)
        #pragma unroll
        for (int ni = 0; ni < 4; ni++)
            #pragma unroll
            for (int r = 0; r < 4; r++) acc[mi][ni][r] = 0.f;

    {
        float4 a0 = *(const float4*)(Aptr);
        float4 a1 = *(const float4*)(Aptr2);
        float4 ta, tb;
        ta.x = to_tf32(a0.x); ta.y = to_tf32(a0.y); ta.z = to_tf32(a0.z); ta.w = to_tf32(a0.w);
        tb.x = to_tf32(a1.x); tb.y = to_tf32(a1.y); tb.z = to_tf32(a1.z); tb.w = to_tf32(a1.w);
        *(float4*)(&As[0][am][ak])      = ta;
        *(float4*)(&As[0][am + 64][ak]) = tb;
        float4 bv;
        bv.x = to_tf32(Bptr[(long long)(bkq + 0) * ldb]);
        bv.y = to_tf32(Bptr[(long long)(bkq + 1) * ldb]);
        bv.z = to_tf32(Bptr[(long long)(bkq + 2) * ldb]);
        bv.w = to_tf32(Bptr[(long long)(bkq + 3) * ldb]);
        *(float4*)(&Bs[0][bn][bkq]) = bv;
    }
    __syncthreads();

    const int nk = K >> 4;
    for (int t = 0; t < nk; t++) {
        const int buf = t & 1;
        float4 ra, ra2; float rb[4];
        if (t + 1 < nk) {
            int k0 = (t + 1) << 4;
            ra  = *(const float4*)(Aptr + k0);
            ra2 = *(const float4*)(Aptr2 + k0);
            #pragma unroll
            for (int j = 0; j < 4; j++)
                rb[j] = Bptr[(long long)(k0 + bkq + j) * ldb];
        }

        #pragma unroll
        for (int ks = 0; ks < 2; ks++) {
            unsigned ao = (unsigned)(buf * ABUF_BYTES + ks * 32);
            unsigned bo = (unsigned)(buf * BBUF_BYTES + ks * 32);
            unsigned af0[4], af1[4], bf0[4], bf1[4];
            LDSM4(af0[0], af0[1], af0[2], af0[3], aaddr0 + ao);
            LDSM4(af1[0], af1[1], af1[2], af1[3], aaddr1 + ao);
            LDSM4(bf0[0], bf0[1], bf0[2], bf0[3], baddr0 + bo);
            LDSM4(bf1[0], bf1[1], bf1[2], bf1[3], baddr1 + bo);
            mma1688(acc[0][0], af0, &bf0[0]);
            mma1688(acc[0][1], af0, &bf0[2]);
            mma1688(acc[0][2], af0, &bf1[0]);
            mma1688(acc[0][3], af0, &bf1[2]);
            mma1688(acc[1][0], af1, &bf0[0]);
            mma1688(acc[1][1], af1, &bf0[2]);
            mma1688(acc[1][2], af1, &bf1[0]);
            mma1688(acc[1][3], af1, &bf1[2]);
        }

        if (t + 1 < nk) {
            const int nb = (t + 1) & 1;
            float4 ta, tb, bv;
            ta.x = to_tf32(ra.x);  ta.y = to_tf32(ra.y);  ta.z = to_tf32(ra.z);  ta.w = to_tf32(ra.w);
            tb.x = to_tf32(ra2.x); tb.y = to_tf32(ra2.y); tb.z = to_tf32(ra2.z); tb.w = to_tf32(ra2.w);
            bv.x = to_tf32(rb[0]); bv.y = to_tf32(rb[1]); bv.z = to_tf32(rb[2]); bv.w = to_tf32(rb[3]);
            *(float4*)(&As[nb][am][ak])      = ta;
            *(float4*)(&As[nb][am + 64][ak]) = tb;
            *(float4*)(&Bs[nb][bn][bkq])     = bv;
            __syncthreads();
        }
    }

    #pragma unroll
    for (int mi = 0; mi < 2; mi++)
        #pragma unroll
        for (int ni = 0; ni < 4; ni++) {
            int r = row0 + wm + mi * 16 + g;
            int c = col0 + wn + ni * 8 + 2 * t4;
            float o0 = acc[mi][ni][0];
            float o1 = acc[mi][ni][1];
            float o2 = acc[mi][ni][2];
            float o3 = acc[mi][ni][3];
            if (bias) {
                o0 += bias[c]; o1 += bias[c + 1];
                o2 += bias[c]; o3 += bias[c + 1];
            }
            if (relu) {
                o0 = fmaxf(o0, 0.f); o1 = fmaxf(o1, 0.f);
                o2 = fmaxf(o2, 0.f); o3 = fmaxf(o3, 0.f);
            }
            *(float2*)(C + (long long)r * ldc + c)       = make_float2(o0, o1);
            *(float2*)(C + (long long)(r + 8) * ldc + c) = make_float2(o2, o3);
        }
}

// Row softmax with key-padding mask.
__global__ __launch_bounds__(256) void softmax_attn(
    float* __restrict__ S, const int* __restrict__ mask)
{
    int row = blockIdx.x;
    int b = row >> 12;
    float* Sp = S + (long long)row * NS;
    const int* mp = mask + b * NS;
    int tid = threadIdx.x;

    float v0 = mp[tid]       ? Sp[tid]       : -1e9f;
    float v1 = mp[tid + 256] ? Sp[tid + 256] : -1e9f;

    __shared__ float red[256];
    red[tid] = fmaxf(v0, v1);
    __syncthreads();
    for (int s = 128; s > 0; s >>= 1) {
        if (tid < s) red[tid] = fmaxf(red[tid], red[tid + s]);
        __syncthreads();
    }
    float m = red[0];
    __syncthreads();

    float e0 = __expf(v0 - m), e1 = __expf(v1 - m);
    red[tid] = e0 + e1;
    __syncthreads();
    for (int s = 128; s > 0; s >>= 1) {
        if (tid < s) red[tid] += red[tid + s];
        __syncthreads();
    }
    float inv = 1.f / red[0];
    Sp[tid]       = e0 * inv;
    Sp[tid + 256] = e1 * inv;
}

// out[row] = LN(x[row] + y[row]) * g + b.
__global__ __launch_bounds__(256) void ln_add(
    const float* __restrict__ X, const float* __restrict__ Y,
    const float* __restrict__ g, const float* __restrict__ be,
    float* __restrict__ O)
{
    int row = blockIdx.x;
    const float* xp = X + (long long)row * DM;
    const float* yp = Y + (long long)row * DM;
    float* op = O + (long long)row * DM;
    int tid = threadIdx.x;

    float a0 = xp[tid] + yp[tid];
    float a1 = xp[tid + 256] + yp[tid + 256];

    __shared__ float r1[256];
    __shared__ float r2[256];
    r1[tid] = a0 + a1;
    r2[tid] = a0 * a0 + a1 * a1;
    __syncthreads();
    for (int s = 128; s > 0; s >>= 1) {
        if (tid < s) { r1[tid] += r1[tid + s]; r2[tid] += r2[tid + s]; }
        __syncthreads();
    }
    float mean = r1[0] * (1.f / DM);
    float var  = r2[0] * (1.f / DM) - mean * mean;
    float rstd = rsqrtf(var + LN_EPS);
    op[tid]       = (a0 - mean) * rstd * g[tid]       + be[tid];
    op[tid + 256] = (a1 - mean) * rstd * g[tid + 256] + be[tid + 256];
}

__global__ void vmul_k(const float* __restrict__ v, const float* __restrict__ w,
                       float* __restrict__ o, int n) {
    int i = blockIdx.x * blockDim.x + threadIdx.x;
    if (i < n) o[i] = v[i] * w[i & (DM - 1)];
}

__global__ __launch_bounds__(256) void softmax_final(
    float* __restrict__ S, const int* __restrict__ vmask,
    const int* __restrict__ qmask, const float* __restrict__ attb)
{
    int row = blockIdx.x;
    int b = row >> 9, i = row & (NS - 1);
    int rowpad = (vmask[b * NS + i] == 0);
    float ab = attb[0];
    float* Sp = S + (long long)row * NS;
    int tid = threadIdx.x;

    float v0 = (rowpad || qmask[b * NS + tid] == 0)       ? -1e9f : Sp[tid] + ab;
    float v1 = (rowpad || qmask[b * NS + tid + 256] == 0) ? -1e9f : Sp[tid + 256] + ab;

    __shared__ float red[256];
    red[tid] = fmaxf(v0, v1);
    __syncthreads();
    for (int s = 128; s > 0; s >>= 1) {
        if (tid < s) red[tid] = fmaxf(red[tid], red[tid + s]);
        __syncthreads();
    }
    float m = red[0];
    __syncthreads();

    float e0 = __expf(v0 - m), e1 = __expf(v1 - m);
    red[tid] = e0 + e1;
    __syncthreads();
    for (int s = 128; s > 0; s >>= 1) {
        if (tid < s) red[tid] += red[tid + s];
        __syncthreads();
    }
    float inv = 1.f / red[0];
    Sp[tid]       = e0 * inv;
    Sp[tid + 256] = e1 * inv;
}

__global__ void final_out_k(const float* __restrict__ V, const float* __restrict__ T,
                            float* __restrict__ out) {
    int b = blockIdx.x;
    int k = threadIdx.x;
    const float* vp = V + (long long)b * NS * DM;
    const float* tp = T + (long long)b * NS * DM;
    float acc = 0.f;
    #pragma unroll 4
    for (int i = 0; i < NS; i++)
        acc = fmaf(vp[(long long)i * DM + k], tp[(long long)i * DM + k], acc);
    out[b * DM + k] = acc * (1.f / 512.f);
}

// ------------------------------- host side ---------------------------------

static void run_mha(const float* xq, const float* xkv, const int* mask,
                    const float* w, const float* b,
                    const float* wo, const float* bo,
                    float* QKV, float* SC, float* AO, float* out)
{
    const long long NT = (long long)BB * NS * DM;
    const long long WSTRIDE = (long long)DM * DM;
    const dim3 gP(DM / 128, (BB * NS) / 64, 1);

    if (xq == xkv) {
        // self-attention: fused QKV, z=3
        mma_nn2<<<dim3(DM / 128, (BB * NS) / 64, 3), 128>>>(
            xq, w, b, QKV, DM, DM, DM, DM,
            3, 0, 0, 0, WSTRIDE, 0, NT, DM, 0);
    } else {
        mma_nn2<<<gP, 128>>>(
            xq, w, b, QKV, DM, DM, DM, DM,
            1, 0, 0, 0, 0, 0, 0, DM, 0);
        mma_nn2<<<dim3(DM / 128, (BB * NS) / 64, 2), 128>>>(
            xkv, w + WSTRIDE, b + DM, QKV + NT, DM, DM, DM, DM,
            2, 0, 0, 0, WSTRIDE, 0, NT, DM, 0);
    }

    const float* PQ = QKV;
    const float* PK = QKV + NT;
    const float* PV = QKV + 2 * NT;

    // scores: S[b*8+h] = 0.125 * Qh @ Kh^T
    mma_nt2<<<dim3(NS / 128, NS / 64, BB * NHEAD), 128>>>(
        PQ, PK, SC, DHH, DM, DM, NS,
        NHEAD, (long long)NS * DM, DHH, (long long)NS * DM, DHH,
        (long long)NHEAD * NS * NS, (long long)NS * NS, 0.125f);

    softmax_attn<<<BB * NHEAD * NS, 256>>>(SC, mask);

    // AV: O_h = S @ V_h (N=64) — 128x64 kernel
    mma_nn<<<dim3(1, NS / 128, BB * NHEAD), 256>>>(
        SC, PV, (const float*)nullptr, AO, NS, NS, DM, DM,
        NHEAD, (long long)NHEAD * NS * NS, (long long)NS * NS,
        (long long)NS * DM, DHH,
        (long long)NS * DM, DHH, 0, 0);

    // output projection
    mma_nn2<<<gP, 128>>>(
        AO, wo, bo, out, DM, DM, DM, DM,
        1, 0, 0, 0, 0, 0, 0, DM, 0);
}

extern "C" void kernel_launch(void* const* d_in, const int* in_sizes, int n_in,
                              void* d_out, int out_size)
{
    const float *v_in, *q_in, *attn_w, *attn_b, *attn_wo, *attn_bo;
    const float *ln_g, *ln_b, *fw1, *fb1, *fw2, *fb2, *att_w, *att_b;
    const int *v_mask, *q_mask;

    if (in_sizes[2] == BB * NS) {   // dict order
        v_in    = (const float*)d_in[0];
        q_in    = (const float*)d_in[1];
        v_mask  = (const int*)  d_in[2];
        q_mask  = (const int*)  d_in[3];
        attn_w  = (const float*)d_in[4];
        attn_b  = (const float*)d_in[5];
        attn_wo = (const float*)d_in[6];
        attn_bo = (const float*)d_in[7];
        ln_g    = (const float*)d_in[8];
        ln_b    = (const float*)d_in[9];
        fw1     = (const float*)d_in[10];
        fb1     = (const float*)d_in[11];
        fw2     = (const float*)d_in[12];
        fb2     = (const float*)d_in[13];
        att_w   = (const float*)d_in[14];
        att_b   = (const float*)d_in[15];
    } else {                        // signature order
        v_in    = (const float*)d_in[0];
        q_in    = (const float*)d_in[1];
        attn_w  = (const float*)d_in[2];
        attn_b  = (const float*)d_in[3];
        attn_wo = (const float*)d_in[4];
        attn_bo = (const float*)d_in[5];
        ln_g    = (const float*)d_in[6];
        ln_b    = (const float*)d_in[7];
        fw1     = (const float*)d_in[8];
        fb1     = (const float*)d_in[9];
        fw2     = (const float*)d_in[10];
        fb2     = (const float*)d_in[11];
        att_w   = (const float*)d_in[12];
        att_b   = (const float*)d_in[13];
        v_mask  = (const int*)  d_in[14];
        q_mask  = (const int*)  d_in[15];
    }

    float *V, *Q, *QKV, *SC, *AO, *TMP, *VA, *QA, *VQ, *QV, *FFN;
    cudaGetSymbolAddress((void**)&V,   g_v);
    cudaGetSymbolAddress((void**)&Q,   g_q);
    cudaGetSymbolAddress((void**)&QKV, g_qkv);
    cudaGetSymbolAddress((void**)&SC,  g_sc);
    cudaGetSymbolAddress((void**)&AO,  g_ao);
    cudaGetSymbolAddress((void**)&TMP, g_tmp);
    cudaGetSymbolAddress((void**)&VA,  g_va);
    cudaGetSymbolAddress((void**)&QA,  g_qa);
    cudaGetSymbolAddress((void**)&VQ,  g_vq);
    cudaGetSymbolAddress((void**)&QV,  g_qv);
    cudaGetSymbolAddress((void**)&FFN, g_ffn);

    const int NTOK = BB * NS * DM;
    const long long NT = (long long)NTOK;
    const long long SBATCH = (long long)NS * DM;
    copy_k<<<(NTOK + 255) / 256, 256>>>(v_in, V, NTOK);
    copy_k<<<(NTOK + 255) / 256, 256>>>(q_in, Q, NTOK);

    const int rows = BB * NS;

    for (int i = 0; i < NLAY; i++) {
        const float* aw  = attn_w  + (long long)i * 4 * 3 * DM * DM;
        const float* ab  = attn_b  + (long long)i * 4 * 3 * DM;
        const float* awo = attn_wo + (long long)i * 4 * DM * DM;
        const float* abo = attn_bo + (long long)i * 4 * DM;
        const float* lg  = ln_g + (long long)i * 6 * DM;
        const float* lb  = ln_b + (long long)i * 6 * DM;

        run_mha(V, V, v_mask, aw, ab, awo, abo, QKV, SC, AO, TMP);
        ln_add<<<rows, 256>>>(V, TMP, lg, lb, VA);

        run_mha(Q, Q, q_mask,
                aw + 3ll * DM * DM, ab + 3 * DM, awo + (long long)DM * DM, abo + DM,
                QKV, SC, AO, TMP);
        ln_add<<<rows, 256>>>(Q, TMP, lg + DM, lb + DM, QA);

        run_mha(VA, QA, q_mask,
                aw + 6ll * DM * DM, ab + 6 * DM, awo + 2ll * DM * DM, abo + 2 * DM,
                QKV, SC, AO, VQ);
        run_mha(QA, VQ, v_mask,
                aw + 9ll * DM * DM, ab + 9 * DM, awo + 3ll * DM * DM, abo + 3 * DM,
                QKV, SC, AO, QV);

        ln_add<<<rows, 256>>>(V, VQ, lg + 2 * DM, lb + 2 * DM, V);
        ln_add<<<rows, 256>>>(Q, QV, lg + 3 * DM, lb + 3 * DM, Q);

        const float* w1v = fw1 + (long long)i * 2 * DM * DFF;
        const float* b1v = fb1 + (long long)i * 2 * DFF;
        const float* w2v = fw2 + (long long)i * 2 * DFF * DM;
        const float* b2v = fb2 + (long long)i * 2 * DM;

        mma_nn2<<<dim3(DFF / 128, rows / 64, 1), 128>>>(
            V, w1v, b1v, FFN, DM, DM, DFF, DFF,
            1, 0, 0, 0, 0, 0, 0, 0, 1);
        mma_nn2<<<dim3(DM / 128, rows / 64, 1), 128>>>(
            FFN, w2v, b2v, TMP, DFF, DFF, DM, DM,
            1, 0, 0, 0, 0, 0, 0, 0, 0);
        ln_add<<<rows, 256>>>(V, TMP, lg + 4 * DM, lb + 4 * DM, V);

        mma_nn2<<<dim3(DFF / 128, rows / 64, 1), 128>>>(
            Q, w1v + (long long)DM * DFF, b1v + DFF, FFN, DM, DM, DFF, DFF,
            1, 0, 0, 0, 0, 0, 0, 0, 1);
        mma_nn2<<<dim3(DM / 128, rows / 64, 1), 128>>>(
            FFN, w2v + (long long)DFF * DM, b2v + DM, TMP, DFF, DFF, DM, DM,
            1, 0, 0, 0, 0, 0, 0, 0, 0);
        ln_add<<<rows, 256>>>(Q, TMP, lg + 5 * DM, lb + 5 * DM, Q);
    }

    // Final bilinear attention pooling.
    float* PQs = QKV;
    float* Ts  = QKV + NT;
    vmul_k<<<(NTOK + 255) / 256, 256>>>(V, att_w, PQs, NTOK);
    mma_nt2<<<dim3(NS / 128, NS / 64, BB), 128>>>(
        PQs, Q, SC, DM, DM, DM, NS,
        1, SBATCH, 0, SBATCH, 0, (long long)NS * NS, 0, 1.0f);
    softmax_final<<<BB * NS, 256>>>(SC, v_mask, q_mask, att_b);
    mma_nn2<<<dim3(DM / 128, NS / 64, BB), 128>>>(
        SC, Q, (const float*)nullptr, Ts, NS, NS, DM, DM,
        1, (long long)NS * NS, 0, SBATCH, 0, SBATCH, 0, 0, 0);
    final_out_k<<<BB, 512>>>(V, Ts, (float*)d_out);
}

// round 10
// speedup vs baseline: 3.4456x; 1.2005x over previous
#include <cuda_runtime.h>
#include <cuda_bf16.h>
#include <cuda_fp16.h>
#include <cstdint>

// ---------------------------------------------------------------------------
// CoAttention R9: fp16 smem + mma.m16n8k16 (fp32 accum). gmem stays fp32.
// ---------------------------------------------------------------------------

#define BB    8
#define NS    512
#define DM    512
#define NHEAD 8
#define DHH   64
#define DFF   2048
#define NLAY  4
#define LN_EPS 1e-5f

// ------------------------------- scratch -----------------------------------
__device__ float g_v  [BB*NS*DM];
__device__ float g_q  [BB*NS*DM];
__device__ float g_qkv[3*BB*NS*DM];
__device__ float g_sc [BB*NHEAD*NS*NS];
__device__ float g_ao [BB*NS*DM];
__device__ float g_tmp[BB*NS*DM];
__device__ float g_va [BB*NS*DM];
__device__ float g_qa [BB*NS*DM];
__device__ float g_vq [BB*NS*DM];
__device__ float g_qv [BB*NS*DM];
__device__ float g_ffn[BB*NS*DFF];

// ------------------------------- helpers -----------------------------------

__device__ __forceinline__ unsigned f2h2(float a, float b) {
    __half2 h = __floats2half2_rn(a, b);
    return *reinterpret_cast<unsigned*>(&h);
}

__device__ __forceinline__ void mma16816(float* c, const unsigned* a, const unsigned* b) {
    asm volatile(
        "mma.sync.aligned.m16n8k16.row.col.f32.f16.f16.f32 "
        "{%0,%1,%2,%3}, {%4,%5,%6,%7}, {%8,%9}, {%0,%1,%2,%3};\n"
        : "+f"(c[0]), "+f"(c[1]), "+f"(c[2]), "+f"(c[3])
        : "r"(a[0]), "r"(a[1]), "r"(a[2]), "r"(a[3]), "r"(b[0]), "r"(b[1]));
}

#define LDSM4(r0, r1, r2, r3, addr) \
    asm volatile("ldmatrix.sync.aligned.m8n8.x4.shared.b16 {%0,%1,%2,%3}, [%4];" \
        : "=r"(r0), "=r"(r1), "=r"(r2), "=r"(r3) : "r"(addr))

// half strides: 40 halves = 80B row stride; conflict-free, 16B aligned
#define SH 40
#define ROWB 80
// 64x128 kernel buffers (bytes)
#define A2BUF (64  * ROWB)
#define B2BUF (128 * ROWB)
// AV kernel buffers
#define AVABUF (128 * ROWB)
#define AVBBUF (64  * ROWB)

// ------------------------------- kernels -----------------------------------

__global__ void copy_k(const float* __restrict__ src, float* __restrict__ dst, int n) {
    int i = blockIdx.x * blockDim.x + threadIdx.x;
    if (i < n) dst[i] = src[i];
}

// ======== NN GEMM fp16: block 64x128, BK=32, 128 thr, warp 32x64 ===========
__global__ __launch_bounds__(128) void mma_nn2h(
    const float* __restrict__ A, const float* __restrict__ B,
    const float* __restrict__ bias, float* __restrict__ C,
    int K, int lda, int ldb, int ldc,
    int zdiv, long long sA1, long long sA2, long long sB1, long long sB2,
    long long sC1, long long sC2, long long sBias, int relu)
{
    int z = blockIdx.z;
    int z1 = z / zdiv, z2 = z - z1 * zdiv;
    A += z1 * sA1 + (long long)z2 * sA2;
    B += z1 * sB1 + (long long)z2 * sB2;
    C += z1 * sC1 + (long long)z2 * sC2;
    if (bias) bias += (long long)z * sBias;

    __shared__ __align__(16) __half As[2][64][SH];    // [m][k]
    __shared__ __align__(16) __half Bs[2][128][SH];   // [n][k]

    const int tid = threadIdx.x;
    const int wid = tid >> 5, lane = tid & 31;
    const int wm = (wid >> 1) * 32, wn = (wid & 1) * 64;
    const int g = lane >> 2, t4 = lane & 3;
    const int row0 = blockIdx.y * 64, col0 = blockIdx.x * 128;

    // A loader: row = tid>>1, kh = (tid&1)*16 (16 floats per thread)
    const int a_r = tid >> 1, a_kh = (tid & 1) * 16;
    const float* Aptr = A + (long long)(row0 + a_r) * lda + a_kh;
    // B loader: column n = tid, 32 strided k
    const float* Bptr = B + col0 + tid;

    const int lr = lane & 7, sel = lane >> 3;
    unsigned as0 = (unsigned)__cvta_generic_to_shared(&As[0][0][0]);
    unsigned bs0 = (unsigned)__cvta_generic_to_shared(&Bs[0][0][0]);
    unsigned aaddr = as0 + (unsigned)((wm + (sel & 1) * 8 + lr) * ROWB + (sel >> 1) * 16);
    unsigned baddr[4];
    #pragma unroll
    for (int j = 0; j < 4; j++)
        baddr[j] = bs0 + (unsigned)((wn + j * 16 + (sel >> 1) * 8 + lr) * ROWB + (sel & 1) * 16);

    float acc[2][8][4];
    #pragma unroll
    for (int mi = 0; mi < 2; mi++)
        #pragma unroll
        for (int ni = 0; ni < 8; ni++)
            #pragma unroll
            for (int r = 0; r < 4; r++) acc[mi][ni][r] = 0.f;

    // preload tile 0
    {
        unsigned ah[8], bh[16];
        #pragma unroll
        for (int i = 0; i < 4; i++) {
            float4 v = *(const float4*)(Aptr + i * 4);
            ah[2 * i]     = f2h2(v.x, v.y);
            ah[2 * i + 1] = f2h2(v.z, v.w);
        }
        #pragma unroll
        for (int j = 0; j < 16; j++)
            bh[j] = f2h2(Bptr[(long long)(2 * j) * ldb], Bptr[(long long)(2 * j + 1) * ldb]);
        *(uint4*)(&As[0][a_r][a_kh])     = make_uint4(ah[0], ah[1], ah[2], ah[3]);
        *(uint4*)(&As[0][a_r][a_kh + 8]) = make_uint4(ah[4], ah[5], ah[6], ah[7]);
        *(uint4*)(&Bs[0][tid][0])  = make_uint4(bh[0],  bh[1],  bh[2],  bh[3]);
        *(uint4*)(&Bs[0][tid][8])  = make_uint4(bh[4],  bh[5],  bh[6],  bh[7]);
        *(uint4*)(&Bs[0][tid][16]) = make_uint4(bh[8],  bh[9],  bh[10], bh[11]);
        *(uint4*)(&Bs[0][tid][24]) = make_uint4(bh[12], bh[13], bh[14], bh[15]);
    }
    __syncthreads();

    const int nk = K >> 5;
    for (int t = 0; t < nk; t++) {
        const int buf = t & 1;
        unsigned ah[8], bh[16];
        if (t + 1 < nk) {
            int k0 = (t + 1) << 5;
            #pragma unroll
            for (int i = 0; i < 4; i++) {
                float4 v = *(const float4*)(Aptr + k0 + i * 4);
                ah[2 * i]     = f2h2(v.x, v.y);
                ah[2 * i + 1] = f2h2(v.z, v.w);
            }
            #pragma unroll
            for (int j = 0; j < 16; j++)
                bh[j] = f2h2(Bptr[(long long)(k0 + 2 * j) * ldb],
                             Bptr[(long long)(k0 + 2 * j + 1) * ldb]);
        }

        #pragma unroll
        for (int ks = 0; ks < 2; ks++) {
            unsigned ko = (unsigned)(ks * 32);           // 16 halves = 32B
            unsigned ao = (unsigned)(buf * A2BUF) + ko;
            unsigned bo = (unsigned)(buf * B2BUF) + ko;
            unsigned af0[4], af1[4], bf[4][4];
            LDSM4(af0[0], af0[1], af0[2], af0[3], aaddr + ao);
            LDSM4(af1[0], af1[1], af1[2], af1[3], aaddr + 16u * ROWB + ao);
            #pragma unroll
            for (int j = 0; j < 4; j++)
                LDSM4(bf[j][0], bf[j][1], bf[j][2], bf[j][3], baddr[j] + bo);
            #pragma unroll
            for (int j = 0; j < 4; j++) {
                mma16816(acc[0][2 * j],     af0, &bf[j][0]);
                mma16816(acc[0][2 * j + 1], af0, &bf[j][2]);
                mma16816(acc[1][2 * j],     af1, &bf[j][0]);
                mma16816(acc[1][2 * j + 1], af1, &bf[j][2]);
            }
        }

        if (t + 1 < nk) {
            const int nb = (t + 1) & 1;
            *(uint4*)(&As[nb][a_r][a_kh])     = make_uint4(ah[0], ah[1], ah[2], ah[3]);
            *(uint4*)(&As[nb][a_r][a_kh + 8]) = make_uint4(ah[4], ah[5], ah[6], ah[7]);
            *(uint4*)(&Bs[nb][tid][0])  = make_uint4(bh[0],  bh[1],  bh[2],  bh[3]);
            *(uint4*)(&Bs[nb][tid][8])  = make_uint4(bh[4],  bh[5],  bh[6],  bh[7]);
            *(uint4*)(&Bs[nb][tid][16]) = make_uint4(bh[8],  bh[9],  bh[10], bh[11]);
            *(uint4*)(&Bs[nb][tid][24]) = make_uint4(bh[12], bh[13], bh[14], bh[15]);
            __syncthreads();
        }
    }

    #pragma unroll
    for (int mi = 0; mi < 2; mi++)
        #pragma unroll
        for (int ni = 0; ni < 8; ni++) {
            int r = row0 + wm + mi * 16 + g;
            int c = col0 + wn + ni * 8 + 2 * t4;
            float b0v = 0.f, b1v = 0.f;
            if (bias) { b0v = bias[c]; b1v = bias[c + 1]; }
            float o0 = acc[mi][ni][0] + b0v;
            float o1 = acc[mi][ni][1] + b1v;
            float o2 = acc[mi][ni][2] + b0v;
            float o3 = acc[mi][ni][3] + b1v;
            if (relu) {
                o0 = fmaxf(o0, 0.f); o1 = fmaxf(o1, 0.f);
                o2 = fmaxf(o2, 0.f); o3 = fmaxf(o3, 0.f);
            }
            *(float2*)(C + (long long)r * ldc + c)       = make_float2(o0, o1);
            *(float2*)(C + (long long)(r + 8) * ldc + c) = make_float2(o2, o3);
        }
}

// ======== NT GEMM fp16: block 64x128, BK=32, 128 thr, warp 32x64 ===========
__global__ __launch_bounds__(128) void mma_nt2h(
    const float* __restrict__ A, const float* __restrict__ B,
    float* __restrict__ C,
    int K, int lda, int ldb, int ldc,
    int zdiv, long long sA1, long long sA2, long long sB1, long long sB2,
    long long sC1, long long sC2, float scale)
{
    int z = blockIdx.z;
    int z1 = z / zdiv, z2 = z - z1 * zdiv;
    A += z1 * sA1 + (long long)z2 * sA2;
    B += z1 * sB1 + (long long)z2 * sB2;
    C += z1 * sC1 + (long long)z2 * sC2;

    __shared__ __align__(16) __half As[2][64][SH];
    __shared__ __align__(16) __half Bs[2][128][SH];

    const int tid = threadIdx.x;
    const int wid = tid >> 5, lane = tid & 31;
    const int wm = (wid >> 1) * 32, wn = (wid & 1) * 64;
    const int g = lane >> 2, t4 = lane & 3;
    const int row0 = blockIdx.y * 64, col0 = blockIdx.x * 128;

    const int a_r = tid >> 1, a_kh = (tid & 1) * 16;
    const float* Aptr = A + (long long)(row0 + a_r) * lda + a_kh;
    // B loader: row n = tid (ldb-strided), 32 contiguous k per tile... but per
    // thread we need the full 32; split as 2 threads can't (128 thr,128 rows).
    const float* Bptr = B + (long long)(col0 + tid) * ldb;

    const int lr = lane & 7, sel = lane >> 3;
    unsigned as0 = (unsigned)__cvta_generic_to_shared(&As[0][0][0]);
    unsigned bs0 = (unsigned)__cvta_generic_to_shared(&Bs[0][0][0]);
    unsigned aaddr = as0 + (unsigned)((wm + (sel & 1) * 8 + lr) * ROWB + (sel >> 1) * 16);
    unsigned baddr[4];
    #pragma unroll
    for (int j = 0; j < 4; j++)
        baddr[j] = bs0 + (unsigned)((wn + j * 16 + (sel >> 1) * 8 + lr) * ROWB + (sel & 1) * 16);

    float acc[2][8][4];
    #pragma unroll
    for (int mi = 0; mi < 2; mi++)
        #pragma unroll
        for (int ni = 0; ni < 8; ni++)
            #pragma unroll
            for (int r = 0; r < 4; r++) acc[mi][ni][r] = 0.f;

    {
        unsigned ah[8], bh[16];
        #pragma unroll
        for (int i = 0; i < 4; i++) {
            float4 v = *(const float4*)(Aptr + i * 4);
            ah[2 * i]     = f2h2(v.x, v.y);
            ah[2 * i + 1] = f2h2(v.z, v.w);
        }
        #pragma unroll
        for (int i = 0; i < 8; i++) {
            float4 v = *(const float4*)(Bptr + i * 4);
            bh[2 * i]     = f2h2(v.x, v.y);
            bh[2 * i + 1] = f2h2(v.z, v.w);
        }
        *(uint4*)(&As[0][a_r][a_kh])     = make_uint4(ah[0], ah[1], ah[2], ah[3]);
        *(uint4*)(&As[0][a_r][a_kh + 8]) = make_uint4(ah[4], ah[5], ah[6], ah[7]);
        *(uint4*)(&Bs[0][tid][0])  = make_uint4(bh[0],  bh[1],  bh[2],  bh[3]);
        *(uint4*)(&Bs[0][tid][8])  = make_uint4(bh[4],  bh[5],  bh[6],  bh[7]);
        *(uint4*)(&Bs[0][tid][16]) = make_uint4(bh[8],  bh[9],  bh[10], bh[11]);
        *(uint4*)(&Bs[0][tid][24]) = make_uint4(bh[12], bh[13], bh[14], bh[15]);
    }
    __syncthreads();

    const int nk = K >> 5;
    for (int t = 0; t < nk; t++) {
        const int buf = t & 1;
        unsigned ah[8], bh[16];
        if (t + 1 < nk) {
            int k0 = (t + 1) << 5;
            #pragma unroll
            for (int i = 0; i < 4; i++) {
                float4 v = *(const float4*)(Aptr + k0 + i * 4);
                ah[2 * i]     = f2h2(v.x, v.y);
                ah[2 * i + 1] = f2h2(v.z, v.w);
            }
            #pragma unroll
            for (int i = 0; i < 8; i++) {
                float4 v = *(const float4*)(Bptr + k0 + i * 4);
                bh[2 * i]     = f2h2(v.x, v.y);
                bh[2 * i + 1] = f2h2(v.z, v.w);
            }
        }

        #pragma unroll
        for (int ks = 0; ks < 2; ks++) {
            unsigned ko = (unsigned)(ks * 32);
            unsigned ao = (unsigned)(buf * A2BUF) + ko;
            unsigned bo = (unsigned)(buf * B2BUF) + ko;
            unsigned af0[4], af1[4], bf[4][4];
            LDSM4(af0[0], af0[1], af0[2], af0[3], aaddr + ao);
            LDSM4(af1[0], af1[1], af1[2], af1[3], aaddr + 16u * ROWB + ao);
            #pragma unroll
            for (int j = 0; j < 4; j++)
                LDSM4(bf[j][0], bf[j][1], bf[j][2], bf[j][3], baddr[j] + bo);
            #pragma unroll
            for (int j = 0; j < 4; j++) {
                mma16816(acc[0][2 * j],     af0, &bf[j][0]);
                mma16816(acc[0][2 * j + 1], af0, &bf[j][2]);
                mma16816(acc[1][2 * j],     af1, &bf[j][0]);
                mma16816(acc[1][2 * j + 1], af1, &bf[j][2]);
            }
        }

        if (t + 1 < nk) {
            const int nb = (t + 1) & 1;
            *(uint4*)(&As[nb][a_r][a_kh])     = make_uint4(ah[0], ah[1], ah[2], ah[3]);
            *(uint4*)(&As[nb][a_r][a_kh + 8]) = make_uint4(ah[4], ah[5], ah[6], ah[7]);
            *(uint4*)(&Bs[nb][tid][0])  = make_uint4(bh[0],  bh[1],  bh[2],  bh[3]);
            *(uint4*)(&Bs[nb][tid][8])  = make_uint4(bh[4],  bh[5],  bh[6],  bh[7]);
            *(uint4*)(&Bs[nb][tid][16]) = make_uint4(bh[8],  bh[9],  bh[10], bh[11]);
            *(uint4*)(&Bs[nb][tid][24]) = make_uint4(bh[12], bh[13], bh[14], bh[15]);
            __syncthreads();
        }
    }

    #pragma unroll
    for (int mi = 0; mi < 2; mi++)
        #pragma unroll
        for (int ni = 0; ni < 8; ni++) {
            int r = row0 + wm + mi * 16 + g;
            int c = col0 + wn + ni * 8 + 2 * t4;
            *(float2*)(C + (long long)r * ldc + c) =
                make_float2(acc[mi][ni][0] * scale, acc[mi][ni][1] * scale);
            *(float2*)(C + (long long)(r + 8) * ldc + c) =
                make_float2(acc[mi][ni][2] * scale, acc[mi][ni][3] * scale);
        }
}

// ======== AV GEMM fp16 (N=64): block 128x64, BK=32, 256 thr, warp 32x32 ====
__global__ __launch_bounds__(256) void mma_nnh_av(
    const float* __restrict__ A, const float* __restrict__ B,
    float* __restrict__ C,
    int K, int lda, int ldb, int ldc,
    int zdiv, long long sA1, long long sA2, long long sB1, long long sB2,
    long long sC1, long long sC2)
{
    int z = blockIdx.z;
    int z1 = z / zdiv, z2 = z - z1 * zdiv;
    A += z1 * sA1 + (long long)z2 * sA2;
    B += z1 * sB1 + (long long)z2 * sB2;
    C += z1 * sC1 + (long long)z2 * sC2;

    __shared__ __align__(16) __half As[2][128][SH];
    __shared__ __align__(16) __half Bs[2][64][SH];

    const int tid = threadIdx.x;
    const int wid = tid >> 5, lane = tid & 31;
    const int wm = (wid >> 1) * 32, wn = (wid & 1) * 32;
    const int g = lane >> 2, t4 = lane & 3;
    const int row0 = blockIdx.y * 128, col0 = blockIdx.x * 64;

    const int a_r = tid >> 1, a_kh = (tid & 1) * 16;
    const float* Aptr = A + (long long)(row0 + a_r) * lda + a_kh;
    // B transpose loader: n = tid&63, kq = (tid>>6)*8
    const int b_n = tid & 63, b_kq = (tid >> 6) * 8;
    const float* Bptr = B + col0 + b_n;

    const int lr = lane & 7, sel = lane >> 3;
    unsigned as0 = (unsigned)__cvta_generic_to_shared(&As[0][0][0]);
    unsigned bs0 = (unsigned)__cvta_generic_to_shared(&Bs[0][0][0]);
    unsigned aaddr = as0 + (unsigned)((wm + (sel & 1) * 8 + lr) * ROWB + (sel >> 1) * 16);
    unsigned baddr0 = bs0 + (unsigned)((wn + (sel >> 1) * 8 + lr) * ROWB + (sel & 1) * 16);
    unsigned baddr1 = baddr0 + 16u * ROWB;

    float acc[2][4][4];
    #pragma unroll
    for (int mi = 0; mi < 2; mi++)
        #pragma unroll
        for (int ni = 0; ni < 4; ni++)
            #pragma unroll
            for (int r = 0; r < 4; r++) acc[mi][ni][r] = 0.f;

    {
        unsigned ah[8], bh[4];
        #pragma unroll
        for (int i = 0; i < 4; i++) {
            float4 v = *(const float4*)(Aptr + i * 4);
            ah[2 * i]     = f2h2(v.x, v.y);
            ah[2 * i + 1] = f2h2(v.z, v.w);
        }
        #pragma unroll
        for (int j = 0; j < 4; j++)
            bh[j] = f2h2(Bptr[(long long)(b_kq + 2 * j) * ldb],
                         Bptr[(long long)(b_kq + 2 * j + 1) * ldb]);
        *(uint4*)(&As[0][a_r][a_kh])     = make_uint4(ah[0], ah[1], ah[2], ah[3]);
        *(uint4*)(&As[0][a_r][a_kh + 8]) = make_uint4(ah[4], ah[5], ah[6], ah[7]);
        *(uint4*)(&Bs[0][b_n][b_kq])     = make_uint4(bh[0], bh[1], bh[2], bh[3]);
    }
    __syncthreads();

    const int nk = K >> 5;
    for (int t = 0; t < nk; t++) {
        const int buf = t & 1;
        unsigned ah[8], bh[4];
        if (t + 1 < nk) {
            int k0 = (t + 1) << 5;
            #pragma unroll
            for (int i = 0; i < 4; i++) {
                float4 v = *(const float4*)(Aptr + k0 + i * 4);
                ah[2 * i]     = f2h2(v.x, v.y);
                ah[2 * i + 1] = f2h2(v.z, v.w);
            }
            #pragma unroll
            for (int j = 0; j < 4; j++)
                bh[j] = f2h2(Bptr[(long long)(k0 + b_kq + 2 * j) * ldb],
                             Bptr[(long long)(k0 + b_kq + 2 * j + 1) * ldb]);
        }

        #pragma unroll
        for (int ks = 0; ks < 2; ks++) {
            unsigned ko = (unsigned)(ks * 32);
            unsigned ao = (unsigned)(buf * AVABUF) + ko;
            unsigned bo = (unsigned)(buf * AVBBUF) + ko;
            unsigned af0[4], af1[4], bf0[4], bf1[4];
            LDSM4(af0[0], af0[1], af0[2], af0[3], aaddr + ao);
            LDSM4(af1[0], af1[1], af1[2], af1[3], aaddr + 16u * ROWB + ao);
            LDSM4(bf0[0], bf0[1], bf0[2], bf0[3], baddr0 + bo);
            LDSM4(bf1[0], bf1[1], bf1[2], bf1[3], baddr1 + bo);
            mma16816(acc[0][0], af0, &bf0[0]);
            mma16816(acc[0][1], af0, &bf0[2]);
            mma16816(acc[0][2], af0, &bf1[0]);
            mma16816(acc[0][3], af0, &bf1[2]);
            mma16816(acc[1][0], af1, &bf0[0]);
            mma16816(acc[1][1], af1, &bf0[2]);
            mma16816(acc[1][2], af1, &bf1[0]);
            mma16816(acc[1][3], af1, &bf1[2]);
        }

        if (t + 1 < nk) {
            const int nb = (t + 1) & 1;
            *(uint4*)(&As[nb][a_r][a_kh])     = make_uint4(ah[0], ah[1], ah[2], ah[3]);
            *(uint4*)(&As[nb][a_r][a_kh + 8]) = make_uint4(ah[4], ah[5], ah[6], ah[7]);
            *(uint4*)(&Bs[nb][b_n][b_kq])     = make_uint4(bh[0], bh[1], bh[2], bh[3]);
            __syncthreads();
        }
    }

    #pragma unroll
    for (int mi = 0; mi < 2; mi++)
        #pragma unroll
        for (int ni = 0; ni < 4; ni++) {
            int r = row0 + wm + mi * 16 + g;
            int c = col0 + wn + ni * 8 + 2 * t4;
            *(float2*)(C + (long long)r * ldc + c) =
                make_float2(acc[mi][ni][0], acc[mi][ni][1]);
            *(float2*)(C + (long long)(r + 8) * ldc + c) =
                make_float2(acc[mi][ni][2], acc[mi][ni][3]);
        }
}

// Row softmax with key-padding mask.
__global__ __launch_bounds__(256) void softmax_attn(
    float* __restrict__ S, const int* __restrict__ mask)
{
    int row = blockIdx.x;
    int b = row >> 12;
    float* Sp = S + (long long)row * NS;
    const int* mp = mask + b * NS;
    int tid = threadIdx.x;

    float v0 = mp[tid]       ? Sp[tid]       : -1e9f;
    float v1 = mp[tid + 256] ? Sp[tid + 256] : -1e9f;

    __shared__ float red[256];
    red[tid] = fmaxf(v0, v1);
    __syncthreads();
    for (int s = 128; s > 0; s >>= 1) {
        if (tid < s) red[tid] = fmaxf(red[tid], red[tid + s]);
        __syncthreads();
    }
    float m = red[0];
    __syncthreads();

    float e0 = __expf(v0 - m), e1 = __expf(v1 - m);
    red[tid] = e0 + e1;
    __syncthreads();
    for (int s = 128; s > 0; s >>= 1) {
        if (tid < s) red[tid] += red[tid + s];
        __syncthreads();
    }
    float inv = 1.f / red[0];
    Sp[tid]       = e0 * inv;
    Sp[tid + 256] = e1 * inv;
}

// out[row] = LN(x[row] + y[row]) * g + b.
__global__ __launch_bounds__(256) void ln_add(
    const float* __restrict__ X, const float* __restrict__ Y,
    const float* __restrict__ g, const float* __restrict__ be,
    float* __restrict__ O)
{
    int row = blockIdx.x;
    const float* xp = X + (long long)row * DM;
    const float* yp = Y + (long long)row * DM;
    float* op = O + (long long)row * DM;
    int tid = threadIdx.x;

    float a0 = xp[tid] + yp[tid];
    float a1 = xp[tid + 256] + yp[tid + 256];

    __shared__ float r1[256];
    __shared__ float r2[256];
    r1[tid] = a0 + a1;
    r2[tid] = a0 * a0 + a1 * a1;
    __syncthreads();
    for (int s = 128; s > 0; s >>= 1) {
        if (tid < s) { r1[tid] += r1[tid + s]; r2[tid] += r2[tid + s]; }
        __syncthreads();
    }
    float mean = r1[0] * (1.f / DM);
    float var  = r2[0] * (1.f / DM) - mean * mean;
    float rstd = rsqrtf(var + LN_EPS);
    op[tid]       = (a0 - mean) * rstd * g[tid]       + be[tid];
    op[tid + 256] = (a1 - mean) * rstd * g[tid + 256] + be[tid + 256];
}

__global__ void vmul_k(const float* __restrict__ v, const float* __restrict__ w,
                       float* __restrict__ o, int n) {
    int i = blockIdx.x * blockDim.x + threadIdx.x;
    if (i < n) o[i] = v[i] * w[i & (DM - 1)];
}

__global__ __launch_bounds__(256) void softmax_final(
    float* __restrict__ S, const int* __restrict__ vmask,
    const int* __restrict__ qmask, const float* __restrict__ attb)
{
    int row = blockIdx.x;
    int b = row >> 9, i = row & (NS - 1);
    int rowpad = (vmask[b * NS + i] == 0);
    float ab = attb[0];
    float* Sp = S + (long long)row * NS;
    int tid = threadIdx.x;

    float v0 = (rowpad || qmask[b * NS + tid] == 0)       ? -1e9f : Sp[tid] + ab;
    float v1 = (rowpad || qmask[b * NS + tid + 256] == 0) ? -1e9f : Sp[tid + 256] + ab;

    __shared__ float red[256];
    red[tid] = fmaxf(v0, v1);
    __syncthreads();
    for (int s = 128; s > 0; s >>= 1) {
        if (tid < s) red[tid] = fmaxf(red[tid], red[tid + s]);
        __syncthreads();
    }
    float m = red[0];
    __syncthreads();

    float e0 = __expf(v0 - m), e1 = __expf(v1 - m);
    red[tid] = e0 + e1;
    __syncthreads();
    for (int s = 128; s > 0; s >>= 1) {
        if (tid < s) red[tid] += red[tid + s];
        __syncthreads();
    }
    float inv = 1.f / red[0];
    Sp[tid]       = e0 * inv;
    Sp[tid + 256] = e1 * inv;
}

__global__ void final_out_k(const float* __restrict__ V, const float* __restrict__ T,
                            float* __restrict__ out) {
    int b = blockIdx.x;
    int k = threadIdx.x;
    const float* vp = V + (long long)b * NS * DM;
    const float* tp = T + (long long)b * NS * DM;
    float acc = 0.f;
    #pragma unroll 4
    for (int i = 0; i < NS; i++)
        acc = fmaf(vp[(long long)i * DM + k], tp[(long long)i * DM + k], acc);
    out[b * DM + k] = acc * (1.f / 512.f);
}

// ------------------------------- host side ---------------------------------

static void run_mha(const float* xq, const float* xkv, const int* mask,
                    const float* w, const float* b,
                    const float* wo, const float* bo,
                    float* QKV, float* SC, float* AO, float* out)
{
    const long long NT = (long long)BB * NS * DM;
    const long long WSTRIDE = (long long)DM * DM;
    const dim3 gP(DM / 128, (BB * NS) / 64, 1);

    if (xq == xkv) {
        mma_nn2h<<<dim3(DM / 128, (BB * NS) / 64, 3), 128>>>(
            xq, w, b, QKV, DM, DM, DM, DM,
            3, 0, 0, 0, WSTRIDE, 0, NT, DM, 0);
    } else {
        mma_nn2h<<<gP, 128>>>(
            xq, w, b, QKV, DM, DM, DM, DM,
            1, 0, 0, 0, 0, 0, 0, DM, 0);
        mma_nn2h<<<dim3(DM / 128, (BB * NS) / 64, 2), 128>>>(
            xkv, w + WSTRIDE, b + DM, QKV + NT, DM, DM, DM, DM,
            2, 0, 0, 0, WSTRIDE, 0, NT, DM, 0);
    }

    const float* PQ = QKV;
    const float* PK = QKV + NT;
    const float* PV = QKV + 2 * NT;

    mma_nt2h<<<dim3(NS / 128, NS / 64, BB * NHEAD), 128>>>(
        PQ, PK, SC, DHH, DM, DM, NS,
        NHEAD, (long long)NS * DM, DHH, (long long)NS * DM, DHH,
        (long long)NHEAD * NS * NS, (long long)NS * NS, 0.125f);

    softmax_attn<<<BB * NHEAD * NS, 256>>>(SC, mask);

    mma_nnh_av<<<dim3(1, NS / 128, BB * NHEAD), 256>>>(
        SC, PV, AO, NS, NS, DM, DM,
        NHEAD, (long long)NHEAD * NS * NS, (long long)NS * NS,
        (long long)NS * DM, DHH,
        (long long)NS * DM, DHH);

    mma_nn2h<<<gP, 128>>>(
        AO, wo, bo, out, DM, DM, DM, DM,
        1, 0, 0, 0, 0, 0, 0, DM, 0);
}

extern "C" void kernel_launch(void* const* d_in, const int* in_sizes, int n_in,
                              void* d_out, int out_size)
{
    const float *v_in, *q_in, *attn_w, *attn_b, *attn_wo, *attn_bo;
    const float *ln_g, *ln_b, *fw1, *fb1, *fw2, *fb2, *att_w, *att_b;
    const int *v_mask, *q_mask;

    if (in_sizes[2] == BB * NS) {   // dict order
        v_in    = (const float*)d_in[0];
        q_in    = (const float*)d_in[1];
        v_mask  = (const int*)  d_in[2];
        q_mask  = (const int*)  d_in[3];
        attn_w  = (const float*)d_in[4];
        attn_b  = (const float*)d_in[5];
        attn_wo = (const float*)d_in[6];
        attn_bo = (const float*)d_in[7];
        ln_g    = (const float*)d_in[8];
        ln_b    = (const float*)d_in[9];
        fw1     = (const float*)d_in[10];
        fb1     = (const float*)d_in[11];
        fw2     = (const float*)d_in[12];
        fb2     = (const float*)d_in[13];
        att_w   = (const float*)d_in[14];
        att_b   = (const float*)d_in[15];
    } else {                        // signature order
        v_in    = (const float*)d_in[0];
        q_in    = (const float*)d_in[1];
        attn_w  = (const float*)d_in[2];
        attn_b  = (const float*)d_in[3];
        attn_wo = (const float*)d_in[4];
        attn_bo = (const float*)d_in[5];
        ln_g    = (const float*)d_in[6];
        ln_b    = (const float*)d_in[7];
        fw1     = (const float*)d_in[8];
        fb1     = (const float*)d_in[9];
        fw2     = (const float*)d_in[10];
        fb2     = (const float*)d_in[11];
        att_w   = (const float*)d_in[12];
        att_b   = (const float*)d_in[13];
        v_mask  = (const int*)  d_in[14];
        q_mask  = (const int*)  d_in[15];
    }

    float *V, *Q, *QKV, *SC, *AO, *TMP, *VA, *QA, *VQ, *QV, *FFN;
    cudaGetSymbolAddress((void**)&V,   g_v);
    cudaGetSymbolAddress((void**)&Q,   g_q);
    cudaGetSymbolAddress((void**)&QKV, g_qkv);
    cudaGetSymbolAddress((void**)&SC,  g_sc);
    cudaGetSymbolAddress((void**)&AO,  g_ao);
    cudaGetSymbolAddress((void**)&TMP, g_tmp);
    cudaGetSymbolAddress((void**)&VA,  g_va);
    cudaGetSymbolAddress((void**)&QA,  g_qa);
    cudaGetSymbolAddress((void**)&VQ,  g_vq);
    cudaGetSymbolAddress((void**)&QV,  g_qv);
    cudaGetSymbolAddress((void**)&FFN, g_ffn);

    const int NTOK = BB * NS * DM;
    const long long NT = (long long)NTOK;
    const long long SBATCH = (long long)NS * DM;
    copy_k<<<(NTOK + 255) / 256, 256>>>(v_in, V, NTOK);
    copy_k<<<(NTOK + 255) / 256, 256>>>(q_in, Q, NTOK);

    const int rows = BB * NS;

    for (int i = 0; i < NLAY; i++) {
        const float* aw  = attn_w  + (long long)i * 4 * 3 * DM * DM;
        const float* ab  = attn_b  + (long long)i * 4 * 3 * DM;
        const float* awo = attn_wo + (long long)i * 4 * DM * DM;
        const float* abo = attn_bo + (long long)i * 4 * DM;
        const float* lg  = ln_g + (long long)i * 6 * DM;
        const float* lb  = ln_b + (long long)i * 6 * DM;

        run_mha(V, V, v_mask, aw, ab, awo, abo, QKV, SC, AO, TMP);
        ln_add<<<rows, 256>>>(V, TMP, lg, lb, VA);

        run_mha(Q, Q, q_mask,
                aw + 3ll * DM * DM, ab + 3 * DM, awo + (long long)DM * DM, abo + DM,
                QKV, SC, AO, TMP);
        ln_add<<<rows, 256>>>(Q, TMP, lg + DM, lb + DM, QA);

        run_mha(VA, QA, q_mask,
                aw + 6ll * DM * DM, ab + 6 * DM, awo + 2ll * DM * DM, abo + 2 * DM,
                QKV, SC, AO, VQ);
        run_mha(QA, VQ, v_mask,
                aw + 9ll * DM * DM, ab + 9 * DM, awo + 3ll * DM * DM, abo + 3 * DM,
                QKV, SC, AO, QV);

        ln_add<<<rows, 256>>>(V, VQ, lg + 2 * DM, lb + 2 * DM, V);
        ln_add<<<rows, 256>>>(Q, QV, lg + 3 * DM, lb + 3 * DM, Q);

        const float* w1v = fw1 + (long long)i * 2 * DM * DFF;
        const float* b1v = fb1 + (long long)i * 2 * DFF;
        const float* w2v = fw2 + (long long)i * 2 * DFF * DM;
        const float* b2v = fb2 + (long long)i * 2 * DM;

        mma_nn2h<<<dim3(DFF / 128, rows / 64, 1), 128>>>(
            V, w1v, b1v, FFN, DM, DM, DFF, DFF,
            1, 0, 0, 0, 0, 0, 0, 0, 1);
        mma_nn2h<<<dim3(DM / 128, rows / 64, 1), 128>>>(
            FFN, w2v, b2v, TMP, DFF, DFF, DM, DM,
            1, 0, 0, 0, 0, 0, 0, 0, 0);
        ln_add<<<rows, 256>>>(V, TMP, lg + 4 * DM, lb + 4 * DM, V);

        mma_nn2h<<<dim3(DFF / 128, rows / 64, 1), 128>>>(
            Q, w1v + (long long)DM * DFF, b1v + DFF, FFN, DM, DM, DFF, DFF,
            1, 0, 0, 0, 0, 0, 0, 0, 1);
        mma_nn2h<<<dim3(DM / 128, rows / 64, 1), 128>>>(
            FFN, w2v + (long long)DFF * DM, b2v + DM, TMP, DFF, DFF, DM, DM,
            1, 0, 0, 0, 0, 0, 0, 0, 0);
        ln_add<<<rows, 256>>>(Q, TMP, lg + 5 * DM, lb + 5 * DM, Q);
    }

    // Final bilinear attention pooling.
    float* PQs = QKV;
    float* Ts  = QKV + NT;
    vmul_k<<<(NTOK + 255) / 256, 256>>>(V, att_w, PQs, NTOK);
    mma_nt2h<<<dim3(NS / 128, NS / 64, BB), 128>>>(
        PQs, Q, SC, DM, DM, DM, NS,
        1, SBATCH, 0, SBATCH, 0, (long long)NS * NS, 0, 1.0f);
    softmax_final<<<BB * NS, 256>>>(SC, v_mask, q_mask, att_b);
    mma_nn2h<<<dim3(DM / 128, NS / 64, BB), 128>>>(
        SC, Q, (const float*)nullptr, Ts, NS, NS, DM, DM,
        1, (long long)NS * NS, 0, SBATCH, 0, SBATCH, 0, 0, 0);
    final_out_k<<<BB, 512>>>(V, Ts, (float*)d_out);
}

// round 11
// speedup vs baseline: 4.3605x; 1.2655x over previous
#include <cuda_runtime.h>
#include <cuda_bf16.h>
#include <cuda_fp16.h>
#include <cstdint>

// ---------------------------------------------------------------------------
// CoAttention R10: R9 fp16 GEMMs + fused flash-style attention
// (QK^T + masked softmax + PV in one kernel; SC never touches gmem).
// ---------------------------------------------------------------------------

#define BB    8
#define NS    512
#define DM    512
#define NHEAD 8
#define DHH   64
#define DFF   2048
#define NLAY  4
#define LN_EPS 1e-5f

// ------------------------------- scratch -----------------------------------
__device__ float g_v  [BB*NS*DM];
__device__ float g_q  [BB*NS*DM];
__device__ float g_qkv[3*BB*NS*DM];
__device__ float g_sc [BB*NS*NS];        // final bilinear scores only
__device__ float g_ao [BB*NS*DM];
__device__ float g_tmp[BB*NS*DM];
__device__ float g_va [BB*NS*DM];
__device__ float g_qa [BB*NS*DM];
__device__ float g_vq [BB*NS*DM];
__device__ float g_qv [BB*NS*DM];
__device__ float g_ffn[BB*NS*DFF];

// ------------------------------- helpers -----------------------------------

__device__ __forceinline__ unsigned f2h2(float a, float b) {
    __half2 h = __floats2half2_rn(a, b);
    return *reinterpret_cast<unsigned*>(&h);
}

__device__ __forceinline__ void mma16816(float* c, const unsigned* a, const unsigned* b) {
    asm volatile(
        "mma.sync.aligned.m16n8k16.row.col.f32.f16.f16.f32 "
        "{%0,%1,%2,%3}, {%4,%5,%6,%7}, {%8,%9}, {%0,%1,%2,%3};\n"
        : "+f"(c[0]), "+f"(c[1]), "+f"(c[2]), "+f"(c[3])
        : "r"(a[0]), "r"(a[1]), "r"(a[2]), "r"(a[3]), "r"(b[0]), "r"(b[1]));
}

#define LDSM4(r0, r1, r2, r3, addr) \
    asm volatile("ldmatrix.sync.aligned.m8n8.x4.shared.b16 {%0,%1,%2,%3}, [%4];" \
        : "=r"(r0), "=r"(r1), "=r"(r2), "=r"(r3) : "r"(addr))

// GEMM smem strides (halves)
#define SH 40
#define ROWB 80
#define A2BUF (64  * ROWB)
#define B2BUF (128 * ROWB)

// flash-attention smem layout (bytes)
#define FA_KSTRB 144    // Q/K row stride: 72 halves
#define FA_VSTRB 272    // Vt row stride: 136 halves
#define FA_PSTRB 1040   // Ps row stride: 520 halves
#define FA_QS   0
#define FA_KV   (FA_QS + 64 * FA_KSTRB)           //  9216
#define FA_PS   (FA_KV + 128 * FA_KSTRB)          // 27648
#define FA_MSK  (FA_PS + 64 * FA_PSTRB)           // 94208
#define FA_RMAX (FA_MSK + 512 * 4)                // 96256
#define FA_SMEM (FA_RMAX + 64 * 4)                // 96512

// ------------------------------- kernels -----------------------------------

__global__ void copy_k(const float* __restrict__ src, float* __restrict__ dst, int n) {
    int i = blockIdx.x * blockDim.x + threadIdx.x;
    if (i < n) dst[i] = src[i];
}

// ======== NN GEMM fp16: block 64x128, BK=32, 128 thr, warp 32x64 ===========
__global__ __launch_bounds__(128) void mma_nn2h(
    const float* __restrict__ A, const float* __restrict__ B,
    const float* __restrict__ bias, float* __restrict__ C,
    int K, int lda, int ldb, int ldc,
    int zdiv, long long sA1, long long sA2, long long sB1, long long sB2,
    long long sC1, long long sC2, long long sBias, int relu)
{
    int z = blockIdx.z;
    int z1 = z / zdiv, z2 = z - z1 * zdiv;
    A += z1 * sA1 + (long long)z2 * sA2;
    B += z1 * sB1 + (long long)z2 * sB2;
    C += z1 * sC1 + (long long)z2 * sC2;
    if (bias) bias += (long long)z * sBias;

    __shared__ __align__(16) __half As[2][64][SH];
    __shared__ __align__(16) __half Bs[2][128][SH];

    const int tid = threadIdx.x;
    const int wid = tid >> 5, lane = tid & 31;
    const int wm = (wid >> 1) * 32, wn = (wid & 1) * 64;
    const int g = lane >> 2, t4 = lane & 3;
    const int row0 = blockIdx.y * 64, col0 = blockIdx.x * 128;

    const int a_r = tid >> 1, a_kh = (tid & 1) * 16;
    const float* Aptr = A + (long long)(row0 + a_r) * lda + a_kh;
    const float* Bptr = B + col0 + tid;

    const int lr = lane & 7, sel = lane >> 3;
    unsigned as0 = (unsigned)__cvta_generic_to_shared(&As[0][0][0]);
    unsigned bs0 = (unsigned)__cvta_generic_to_shared(&Bs[0][0][0]);
    unsigned aaddr = as0 + (unsigned)((wm + (sel & 1) * 8 + lr) * ROWB + (sel >> 1) * 16);
    unsigned baddr[4];
    #pragma unroll
    for (int j = 0; j < 4; j++)
        baddr[j] = bs0 + (unsigned)((wn + j * 16 + (sel >> 1) * 8 + lr) * ROWB + (sel & 1) * 16);

    float acc[2][8][4];
    #pragma unroll
    for (int mi = 0; mi < 2; mi++)
        #pragma unroll
        for (int ni = 0; ni < 8; ni++)
            #pragma unroll
            for (int r = 0; r < 4; r++) acc[mi][ni][r] = 0.f;

    {
        unsigned ah[8], bh[16];
        #pragma unroll
        for (int i = 0; i < 4; i++) {
            float4 v = *(const float4*)(Aptr + i * 4);
            ah[2 * i]     = f2h2(v.x, v.y);
            ah[2 * i + 1] = f2h2(v.z, v.w);
        }
        #pragma unroll
        for (int j = 0; j < 16; j++)
            bh[j] = f2h2(Bptr[(long long)(2 * j) * ldb], Bptr[(long long)(2 * j + 1) * ldb]);
        *(uint4*)(&As[0][a_r][a_kh])     = make_uint4(ah[0], ah[1], ah[2], ah[3]);
        *(uint4*)(&As[0][a_r][a_kh + 8]) = make_uint4(ah[4], ah[5], ah[6], ah[7]);
        *(uint4*)(&Bs[0][tid][0])  = make_uint4(bh[0],  bh[1],  bh[2],  bh[3]);
        *(uint4*)(&Bs[0][tid][8])  = make_uint4(bh[4],  bh[5],  bh[6],  bh[7]);
        *(uint4*)(&Bs[0][tid][16]) = make_uint4(bh[8],  bh[9],  bh[10], bh[11]);
        *(uint4*)(&Bs[0][tid][24]) = make_uint4(bh[12], bh[13], bh[14], bh[15]);
    }
    __syncthreads();

    const int nk = K >> 5;
    for (int t = 0; t < nk; t++) {
        const int buf = t & 1;
        unsigned ah[8], bh[16];
        if (t + 1 < nk) {
            int k0 = (t + 1) << 5;
            #pragma unroll
            for (int i = 0; i < 4; i++) {
                float4 v = *(const float4*)(Aptr + k0 + i * 4);
                ah[2 * i]     = f2h2(v.x, v.y);
                ah[2 * i + 1] = f2h2(v.z, v.w);
            }
            #pragma unroll
            for (int j = 0; j < 16; j++)
                bh[j] = f2h2(Bptr[(long long)(k0 + 2 * j) * ldb],
                             Bptr[(long long)(k0 + 2 * j + 1) * ldb]);
        }

        #pragma unroll
        for (int ks = 0; ks < 2; ks++) {
            unsigned ko = (unsigned)(ks * 32);
            unsigned ao = (unsigned)(buf * A2BUF) + ko;
            unsigned bo = (unsigned)(buf * B2BUF) + ko;
            unsigned af0[4], af1[4], bf[4][4];
            LDSM4(af0[0], af0[1], af0[2], af0[3], aaddr + ao);
            LDSM4(af1[0], af1[1], af1[2], af1[3], aaddr + 16u * ROWB + ao);
            #pragma unroll
            for (int j = 0; j < 4; j++)
                LDSM4(bf[j][0], bf[j][1], bf[j][2], bf[j][3], baddr[j] + bo);
            #pragma unroll
            for (int j = 0; j < 4; j++) {
                mma16816(acc[0][2 * j],     af0, &bf[j][0]);
                mma16816(acc[0][2 * j + 1], af0, &bf[j][2]);
                mma16816(acc[1][2 * j],     af1, &bf[j][0]);
                mma16816(acc[1][2 * j + 1], af1, &bf[j][2]);
            }
        }

        if (t + 1 < nk) {
            const int nb = (t + 1) & 1;
            *(uint4*)(&As[nb][a_r][a_kh])     = make_uint4(ah[0], ah[1], ah[2], ah[3]);
            *(uint4*)(&As[nb][a_r][a_kh + 8]) = make_uint4(ah[4], ah[5], ah[6], ah[7]);
            *(uint4*)(&Bs[nb][tid][0])  = make_uint4(bh[0],  bh[1],  bh[2],  bh[3]);
            *(uint4*)(&Bs[nb][tid][8])  = make_uint4(bh[4],  bh[5],  bh[6],  bh[7]);
            *(uint4*)(&Bs[nb][tid][16]) = make_uint4(bh[8],  bh[9],  bh[10], bh[11]);
            *(uint4*)(&Bs[nb][tid][24]) = make_uint4(bh[12], bh[13], bh[14], bh[15]);
            __syncthreads();
        }
    }

    #pragma unroll
    for (int mi = 0; mi < 2; mi++)
        #pragma unroll
        for (int ni = 0; ni < 8; ni++) {
            int r = row0 + wm + mi * 16 + g;
            int c = col0 + wn + ni * 8 + 2 * t4;
            float b0v = 0.f, b1v = 0.f;
            if (bias) { b0v = bias[c]; b1v = bias[c + 1]; }
            float o0 = acc[mi][ni][0] + b0v;
            float o1 = acc[mi][ni][1] + b1v;
            float o2 = acc[mi][ni][2] + b0v;
            float o3 = acc[mi][ni][3] + b1v;
            if (relu) {
                o0 = fmaxf(o0, 0.f); o1 = fmaxf(o1, 0.f);
                o2 = fmaxf(o2, 0.f); o3 = fmaxf(o3, 0.f);
            }
            *(float2*)(C + (long long)r * ldc + c)       = make_float2(o0, o1);
            *(float2*)(C + (long long)(r + 8) * ldc + c) = make_float2(o2, o3);
        }
}

// ======== NT GEMM fp16 (final bilinear): block 64x128, BK=32 ===============
__global__ __launch_bounds__(128) void mma_nt2h(
    const float* __restrict__ A, const float* __restrict__ B,
    float* __restrict__ C,
    int K, int lda, int ldb, int ldc,
    int zdiv, long long sA1, long long sA2, long long sB1, long long sB2,
    long long sC1, long long sC2, float scale)
{
    int z = blockIdx.z;
    int z1 = z / zdiv, z2 = z - z1 * zdiv;
    A += z1 * sA1 + (long long)z2 * sA2;
    B += z1 * sB1 + (long long)z2 * sB2;
    C += z1 * sC1 + (long long)z2 * sC2;

    __shared__ __align__(16) __half As[2][64][SH];
    __shared__ __align__(16) __half Bs[2][128][SH];

    const int tid = threadIdx.x;
    const int wid = tid >> 5, lane = tid & 31;
    const int wm = (wid >> 1) * 32, wn = (wid & 1) * 64;
    const int g = lane >> 2, t4 = lane & 3;
    const int row0 = blockIdx.y * 64, col0 = blockIdx.x * 128;

    const int a_r = tid >> 1, a_kh = (tid & 1) * 16;
    const float* Aptr = A + (long long)(row0 + a_r) * lda + a_kh;
    const float* Bptr = B + (long long)(col0 + tid) * ldb;

    const int lr = lane & 7, sel = lane >> 3;
    unsigned as0 = (unsigned)__cvta_generic_to_shared(&As[0][0][0]);
    unsigned bs0 = (unsigned)__cvta_generic_to_shared(&Bs[0][0][0]);
    unsigned aaddr = as0 + (unsigned)((wm + (sel & 1) * 8 + lr) * ROWB + (sel >> 1) * 16);
    unsigned baddr[4];
    #pragma unroll
    for (int j = 0; j < 4; j++)
        baddr[j] = bs0 + (unsigned)((wn + j * 16 + (sel >> 1) * 8 + lr) * ROWB + (sel & 1) * 16);

    float acc[2][8][4];
    #pragma unroll
    for (int mi = 0; mi < 2; mi++)
        #pragma unroll
        for (int ni = 0; ni < 8; ni++)
            #pragma unroll
            for (int r = 0; r < 4; r++) acc[mi][ni][r] = 0.f;

    {
        unsigned ah[8], bh[16];
        #pragma unroll
        for (int i = 0; i < 4; i++) {
            float4 v = *(const float4*)(Aptr + i * 4);
            ah[2 * i]     = f2h2(v.x, v.y);
            ah[2 * i + 1] = f2h2(v.z, v.w);
        }
        #pragma unroll
        for (int i = 0; i < 8; i++) {
            float4 v = *(const float4*)(Bptr + i * 4);
            bh[2 * i]     = f2h2(v.x, v.y);
            bh[2 * i + 1] = f2h2(v.z, v.w);
        }
        *(uint4*)(&As[0][a_r][a_kh])     = make_uint4(ah[0], ah[1], ah[2], ah[3]);
        *(uint4*)(&As[0][a_r][a_kh + 8]) = make_uint4(ah[4], ah[5], ah[6], ah[7]);
        *(uint4*)(&Bs[0][tid][0])  = make_uint4(bh[0],  bh[1],  bh[2],  bh[3]);
        *(uint4*)(&Bs[0][tid][8])  = make_uint4(bh[4],  bh[5],  bh[6],  bh[7]);
        *(uint4*)(&Bs[0][tid][16]) = make_uint4(bh[8],  bh[9],  bh[10], bh[11]);
        *(uint4*)(&Bs[0][tid][24]) = make_uint4(bh[12], bh[13], bh[14], bh[15]);
    }
    __syncthreads();

    const int nk = K >> 5;
    for (int t = 0; t < nk; t++) {
        const int buf = t & 1;
        unsigned ah[8], bh[16];
        if (t + 1 < nk) {
            int k0 = (t + 1) << 5;
            #pragma unroll
            for (int i = 0; i < 4; i++) {
                float4 v = *(const float4*)(Aptr + k0 + i * 4);
                ah[2 * i]     = f2h2(v.x, v.y);
                ah[2 * i + 1] = f2h2(v.z, v.w);
            }
            #pragma unroll
            for (int i = 0; i < 8; i++) {
                float4 v = *(const float4*)(Bptr + k0 + i * 4);
                bh[2 * i]     = f2h2(v.x, v.y);
                bh[2 * i + 1] = f2h2(v.z, v.w);
            }
        }

        #pragma unroll
        for (int ks = 0; ks < 2; ks++) {
            unsigned ko = (unsigned)(ks * 32);
            unsigned ao = (unsigned)(buf * A2BUF) + ko;
            unsigned bo = (unsigned)(buf * B2BUF) + ko;
            unsigned af0[4], af1[4], bf[4][4];
            LDSM4(af0[0], af0[1], af0[2], af0[3], aaddr + ao);
            LDSM4(af1[0], af1[1], af1[2], af1[3], aaddr + 16u * ROWB + ao);
            #pragma unroll
            for (int j = 0; j < 4; j++)
                LDSM4(bf[j][0], bf[j][1], bf[j][2], bf[j][3], baddr[j] + bo);
            #pragma unroll
            for (int j = 0; j < 4; j++) {
                mma16816(acc[0][2 * j],     af0, &bf[j][0]);
                mma16816(acc[0][2 * j + 1], af0, &bf[j][2]);
                mma16816(acc[1][2 * j],     af1, &bf[j][0]);
                mma16816(acc[1][2 * j + 1], af1, &bf[j][2]);
            }
        }

        if (t + 1 < nk) {
            const int nb = (t + 1) & 1;
            *(uint4*)(&As[nb][a_r][a_kh])     = make_uint4(ah[0], ah[1], ah[2], ah[3]);
            *(uint4*)(&As[nb][a_r][a_kh + 8]) = make_uint4(ah[4], ah[5], ah[6], ah[7]);
            *(uint4*)(&Bs[nb][tid][0])  = make_uint4(bh[0],  bh[1],  bh[2],  bh[3]);
            *(uint4*)(&Bs[nb][tid][8])  = make_uint4(bh[4],  bh[5],  bh[6],  bh[7]);
            *(uint4*)(&Bs[nb][tid][16]) = make_uint4(bh[8],  bh[9],  bh[10], bh[11]);
            *(uint4*)(&Bs[nb][tid][24]) = make_uint4(bh[12], bh[13], bh[14], bh[15]);
            __syncthreads();
        }
    }

    #pragma unroll
    for (int mi = 0; mi < 2; mi++)
        #pragma unroll
        for (int ni = 0; ni < 8; ni++) {
            int r = row0 + wm + mi * 16 + g;
            int c = col0 + wn + ni * 8 + 2 * t4;
            *(float2*)(C + (long long)r * ldc + c) =
                make_float2(acc[mi][ni][0] * scale, acc[mi][ni][1] * scale);
            *(float2*)(C + (long long)(r + 8) * ldc + c) =
                make_float2(acc[mi][ni][2] * scale, acc[mi][ni][3] * scale);
        }
}

// ======== fused flash attention ============================================
// grid (NS/64, B*H), 128 threads. Q tile 64 x 64; keys in 4 chunks of 128.
__global__ __launch_bounds__(128) void flash_attn(
    const float* __restrict__ Qg, const float* __restrict__ Kg,
    const float* __restrict__ Vg, const int* __restrict__ mask,
    float* __restrict__ Og)
{
    extern __shared__ __align__(16) char smem[];
    __half* Qs = (__half*)(smem + FA_QS);
    __half* KV = (__half*)(smem + FA_KV);
    __half* Ps = (__half*)(smem + FA_PS);
    float*  msk  = (float*)(smem + FA_MSK);
    float*  rmax = (float*)(smem + FA_RMAX);

    const int bh = blockIdx.y;
    const int b = bh >> 3, h = bh & 7;
    const int q0 = blockIdx.x * 64;
    const float* Qp = Qg + (long long)b * NS * DM + h * DHH;
    const float* Kp = Kg + (long long)b * NS * DM + h * DHH;
    const float* Vp = Vg + (long long)b * NS * DM + h * DHH;

    const int tid = threadIdx.x;
    const int wid = tid >> 5, lane = tid & 31;
    const int g = lane >> 2, t4 = lane & 3;
    const int lr = lane & 7, sel = lane >> 3;

    unsigned qs_b = (unsigned)__cvta_generic_to_shared(Qs);
    unsigned kv_b = (unsigned)__cvta_generic_to_shared(KV);
    unsigned ps_b = (unsigned)__cvta_generic_to_shared(Ps);

    // mask bias + rowmax init
    for (int j = tid; j < NS; j += 128)
        msk[j] = mask[b * NS + j] ? 0.f : -1e9f;
    if (tid < 64) rmax[tid] = -1e30f;

    // load Q tile (64 rows x 64): 2 threads per row, 32 floats each
    {
        int r = tid >> 1, kh = (tid & 1) * 32;
        const float* qp = Qp + (long long)(q0 + r) * DM + kh;
        __half* dst = Qs + r * (FA_KSTRB / 2) + kh;
        #pragma unroll
        for (int i = 0; i < 8; i++) {
            float4 v = *(const float4*)(qp + i * 4);
            *(uint2*)(dst + i * 4) = make_uint2(f2h2(v.x, v.y), f2h2(v.z, v.w));
        }
    }
    __syncthreads();

    // fragment base addresses
    unsigned qa = qs_b + (unsigned)((wid * 16 + (sel & 1) * 8 + lr) * FA_KSTRB + (sel >> 1) * 16);

    // ---------------- phase 1: S = mask(scale * Q K^T), row max, store fp16
    for (int c = 0; c < 4; c++) {
        const int j0 = c * 128;
        // load K chunk: thread -> key row j0+tid
        {
            const float* kp = Kp + (long long)(j0 + tid) * DM;
            __half* dst = KV + tid * (FA_KSTRB / 2);
            #pragma unroll
            for (int i = 0; i < 16; i++) {
                float4 v = *(const float4*)(kp + i * 4);
                *(uint2*)(dst + i * 4) = make_uint2(f2h2(v.x, v.y), f2h2(v.z, v.w));
            }
        }
        __syncthreads();

        float s[16][4];
        #pragma unroll
        for (int p = 0; p < 16; p++)
            #pragma unroll
            for (int r = 0; r < 4; r++) s[p][r] = 0.f;

        #pragma unroll
        for (int ks = 0; ks < 4; ks++) {
            unsigned af[4];
            LDSM4(af[0], af[1], af[2], af[3], qa + ks * 32);
            #pragma unroll
            for (int p = 0; p < 8; p++) {
                unsigned bf[4];
                unsigned ba = kv_b + (unsigned)((p * 16 + (sel >> 1) * 8 + lr) * FA_KSTRB
                                                + (sel & 1) * 16) + ks * 32;
                LDSM4(bf[0], bf[1], bf[2], bf[3], ba);
                mma16816(s[2 * p],     af, &bf[0]);
                mma16816(s[2 * p + 1], af, &bf[2]);
            }
        }

        // mask + scale + row max + store
        float lmax0 = -1e30f, lmax1 = -1e30f;
        #pragma unroll
        for (int p = 0; p < 16; p++) {
            int col = j0 + p * 8 + 2 * t4;
            float m0 = msk[col], m1 = msk[col + 1];
            s[p][0] = s[p][0] * 0.125f + m0;
            s[p][1] = s[p][1] * 0.125f + m1;
            s[p][2] = s[p][2] * 0.125f + m0;
            s[p][3] = s[p][3] * 0.125f + m1;
            lmax0 = fmaxf(lmax0, fmaxf(s[p][0], s[p][1]));
            lmax1 = fmaxf(lmax1, fmaxf(s[p][2], s[p][3]));
        }
        lmax0 = fmaxf(lmax0, __shfl_xor_sync(0xffffffffu, lmax0, 1));
        lmax0 = fmaxf(lmax0, __shfl_xor_sync(0xffffffffu, lmax0, 2));
        lmax1 = fmaxf(lmax1, __shfl_xor_sync(0xffffffffu, lmax1, 1));
        lmax1 = fmaxf(lmax1, __shfl_xor_sync(0xffffffffu, lmax1, 2));
        if (t4 == 0) {
            int r0 = wid * 16 + g;
            rmax[r0]     = fmaxf(rmax[r0],     lmax0);
            rmax[r0 + 8] = fmaxf(rmax[r0 + 8], lmax1);
        }
        {
            __half* row0 = Ps + (wid * 16 + g) * (FA_PSTRB / 2);
            __half* row1 = row0 + 8 * (FA_PSTRB / 2);
            #pragma unroll
            for (int p = 0; p < 16; p++) {
                int col = j0 + p * 8 + 2 * t4;
                *(unsigned*)(row0 + col) = f2h2(s[p][0], s[p][1]);
                *(unsigned*)(row1 + col) = f2h2(s[p][2], s[p][3]);
            }
        }
        __syncthreads();
    }

    // ---------------- phase 2: O = exp(S - m) @ V, row-sum normalize
    const float mrow0 = rmax[wid * 16 + g];
    const float mrow1 = rmax[wid * 16 + g + 8];
    float o[8][4];
    #pragma unroll
    for (int p = 0; p < 8; p++)
        #pragma unroll
        for (int r = 0; r < 4; r++) o[p][r] = 0.f;
    float lsum0 = 0.f, lsum1 = 0.f;

    for (int c = 0; c < 4; c++) {
        const int j0 = c * 128;
        // stage V chunk transposed: Vt[dh 64][key 128], row stride FA_VSTRB
        {
            const float* vp = Vp + (long long)(j0 + tid) * DM;
            __half* base = KV + tid;      // column tid
            #pragma unroll
            for (int i = 0; i < 16; i++) {
                float4 v = *(const float4*)(vp + i * 4);
                base[(4 * i + 0) * (FA_VSTRB / 2)] = __float2half_rn(v.x);
                base[(4 * i + 1) * (FA_VSTRB / 2)] = __float2half_rn(v.y);
                base[(4 * i + 2) * (FA_VSTRB / 2)] = __float2half_rn(v.z);
                base[(4 * i + 3) * (FA_VSTRB / 2)] = __float2half_rn(v.w);
            }
        }
        __syncthreads();

        #pragma unroll
        for (int ks = 0; ks < 8; ks++) {
            unsigned pa = ps_b + (unsigned)((wid * 16 + (sel & 1) * 8 + lr) * FA_PSTRB
                                            + (j0 + ks * 16 + (sel >> 1) * 8) * 2);
            unsigned ar[4];
            LDSM4(ar[0], ar[1], ar[2], ar[3], pa);
            float2 f0 = __half22float2(*(__half2*)&ar[0]);   // row g,   k 0,1
            float2 f1 = __half22float2(*(__half2*)&ar[1]);   // row g+8, k 0,1
            float2 f2 = __half22float2(*(__half2*)&ar[2]);   // row g,   k 8,9
            float2 f3 = __half22float2(*(__half2*)&ar[3]);   // row g+8, k 8,9
            f0.x = __expf(f0.x - mrow0); f0.y = __expf(f0.y - mrow0);
            f1.x = __expf(f1.x - mrow1); f1.y = __expf(f1.y - mrow1);
            f2.x = __expf(f2.x - mrow0); f2.y = __expf(f2.y - mrow0);
            f3.x = __expf(f3.x - mrow1); f3.y = __expf(f3.y - mrow1);
            lsum0 += f0.x + f0.y + f2.x + f2.y;
            lsum1 += f1.x + f1.y + f3.x + f3.y;
            unsigned af[4];
            af[0] = f2h2(f0.x, f0.y);
            af[1] = f2h2(f1.x, f1.y);
            af[2] = f2h2(f2.x, f2.y);
            af[3] = f2h2(f3.x, f3.y);
            #pragma unroll
            for (int p = 0; p < 4; p++) {
                unsigned bf[4];
                unsigned ba = kv_b + (unsigned)((p * 16 + (sel >> 1) * 8 + lr) * FA_VSTRB
                                                + ((sel & 1) * 8 + ks * 16) * 2);
                LDSM4(bf[0], bf[1], bf[2], bf[3], ba);
                mma16816(o[2 * p],     af, &bf[0]);
                mma16816(o[2 * p + 1], af, &bf[2]);
            }
        }
        __syncthreads();
    }

    lsum0 += __shfl_xor_sync(0xffffffffu, lsum0, 1);
    lsum0 += __shfl_xor_sync(0xffffffffu, lsum0, 2);
    lsum1 += __shfl_xor_sync(0xffffffffu, lsum1, 1);
    lsum1 += __shfl_xor_sync(0xffffffffu, lsum1, 2);
    const float inv0 = 1.f / lsum0, inv1 = 1.f / lsum1;

    {
        int r0 = q0 + wid * 16 + g;
        float* out0 = Og + ((long long)b * NS + r0) * DM + h * DHH;
        float* out1 = out0 + 8ll * DM;
        #pragma unroll
        for (int p = 0; p < 8; p++) {
            int cc = p * 8 + 2 * t4;
            *(float2*)(out0 + cc) = make_float2(o[p][0] * inv0, o[p][1] * inv0);
            *(float2*)(out1 + cc) = make_float2(o[p][2] * inv1, o[p][3] * inv1);
        }
    }
}

// out[row] = LN(x[row] + y[row]) * g + b.
__global__ __launch_bounds__(256) void ln_add(
    const float* __restrict__ X, const float* __restrict__ Y,
    const float* __restrict__ g, const float* __restrict__ be,
    float* __restrict__ O)
{
    int row = blockIdx.x;
    const float* xp = X + (long long)row * DM;
    const float* yp = Y + (long long)row * DM;
    float* op = O + (long long)row * DM;
    int tid = threadIdx.x;

    float a0 = xp[tid] + yp[tid];
    float a1 = xp[tid + 256] + yp[tid + 256];

    __shared__ float r1[256];
    __shared__ float r2[256];
    r1[tid] = a0 + a1;
    r2[tid] = a0 * a0 + a1 * a1;
    __syncthreads();
    for (int s = 128; s > 0; s >>= 1) {
        if (tid < s) { r1[tid] += r1[tid + s]; r2[tid] += r2[tid + s]; }
        __syncthreads();
    }
    float mean = r1[0] * (1.f / DM);
    float var  = r2[0] * (1.f / DM) - mean * mean;
    float rstd = rsqrtf(var + LN_EPS);
    op[tid]       = (a0 - mean) * rstd * g[tid]       + be[tid];
    op[tid + 256] = (a1 - mean) * rstd * g[tid + 256] + be[tid + 256];
}

__global__ void vmul_k(const float* __restrict__ v, const float* __restrict__ w,
                       float* __restrict__ o, int n) {
    int i = blockIdx.x * blockDim.x + threadIdx.x;
    if (i < n) o[i] = v[i] * w[i & (DM - 1)];
}

__global__ __launch_bounds__(256) void softmax_final(
    float* __restrict__ S, const int* __restrict__ vmask,
    const int* __restrict__ qmask, const float* __restrict__ attb)
{
    int row = blockIdx.x;
    int b = row >> 9, i = row & (NS - 1);
    int rowpad = (vmask[b * NS + i] == 0);
    float ab = attb[0];
    float* Sp = S + (long long)row * NS;
    int tid = threadIdx.x;

    float v0 = (rowpad || qmask[b * NS + tid] == 0)       ? -1e9f : Sp[tid] + ab;
    float v1 = (rowpad || qmask[b * NS + tid + 256] == 0) ? -1e9f : Sp[tid + 256] + ab;

    __shared__ float red[256];
    red[tid] = fmaxf(v0, v1);
    __syncthreads();
    for (int s = 128; s > 0; s >>= 1) {
        if (tid < s) red[tid] = fmaxf(red[tid], red[tid + s]);
        __syncthreads();
    }
    float m = red[0];
    __syncthreads();

    float e0 = __expf(v0 - m), e1 = __expf(v1 - m);
    red[tid] = e0 + e1;
    __syncthreads();
    for (int s = 128; s > 0; s >>= 1) {
        if (tid < s) red[tid] += red[tid + s];
        __syncthreads();
    }
    float inv = 1.f / red[0];
    Sp[tid]       = e0 * inv;
    Sp[tid + 256] = e1 * inv;
}

__global__ void final_out_k(const float* __restrict__ V, const float* __restrict__ T,
                            float* __restrict__ out) {
    int b = blockIdx.x;
    int k = threadIdx.x;
    const float* vp = V + (long long)b * NS * DM;
    const float* tp = T + (long long)b * NS * DM;
    float acc = 0.f;
    #pragma unroll 4
    for (int i = 0; i < NS; i++)
        acc = fmaf(vp[(long long)i * DM + k], tp[(long long)i * DM + k], acc);
    out[b * DM + k] = acc * (1.f / 512.f);
}

// ------------------------------- host side ---------------------------------

static void run_mha(const float* xq, const float* xkv, const int* mask,
                    const float* w, const float* b,
                    const float* wo, const float* bo,
                    float* QKV, float* AO, float* out)
{
    const long long NT = (long long)BB * NS * DM;
    const long long WSTRIDE = (long long)DM * DM;
    const dim3 gP(DM / 128, (BB * NS) / 64, 1);

    if (xq == xkv) {
        mma_nn2h<<<dim3(DM / 128, (BB * NS) / 64, 3), 128>>>(
            xq, w, b, QKV, DM, DM, DM, DM,
            3, 0, 0, 0, WSTRIDE, 0, NT, DM, 0);
    } else {
        mma_nn2h<<<gP, 128>>>(
            xq, w, b, QKV, DM, DM, DM, DM,
            1, 0, 0, 0, 0, 0, 0, DM, 0);
        mma_nn2h<<<dim3(DM / 128, (BB * NS) / 64, 2), 128>>>(
            xkv, w + WSTRIDE, b + DM, QKV + NT, DM, DM, DM, DM,
            2, 0, 0, 0, WSTRIDE, 0, NT, DM, 0);
    }

    flash_attn<<<dim3(NS / 64, BB * NHEAD), 128, FA_SMEM>>>(
        QKV, QKV + NT, QKV + 2 * NT, mask, AO);

    mma_nn2h<<<gP, 128>>>(
        AO, wo, bo, out, DM, DM, DM, DM,
        1, 0, 0, 0, 0, 0, 0, DM, 0);
}

extern "C" void kernel_launch(void* const* d_in, const int* in_sizes, int n_in,
                              void* d_out, int out_size)
{
    // one-time (pre-capture) attribute set for large dynamic smem
    static bool fa_init = [](){
        cudaFuncSetAttribute(flash_attn,
            cudaFuncAttributeMaxDynamicSharedMemorySize, FA_SMEM);
        return true;
    }();
    (void)fa_init;

    const float *v_in, *q_in, *attn_w, *attn_b, *attn_wo, *attn_bo;
    const float *ln_g, *ln_b, *fw1, *fb1, *fw2, *fb2, *att_w, *att_b;
    const int *v_mask, *q_mask;

    if (in_sizes[2] == BB * NS) {   // dict order
        v_in    = (const float*)d_in[0];
        q_in    = (const float*)d_in[1];
        v_mask  = (const int*)  d_in[2];
        q_mask  = (const int*)  d_in[3];
        attn_w  = (const float*)d_in[4];
        attn_b  = (const float*)d_in[5];
        attn_wo = (const float*)d_in[6];
        attn_bo = (const float*)d_in[7];
        ln_g    = (const float*)d_in[8];
        ln_b    = (const float*)d_in[9];
        fw1     = (const float*)d_in[10];
        fb1     = (const float*)d_in[11];
        fw2     = (const float*)d_in[12];
        fb2     = (const float*)d_in[13];
        att_w   = (const float*)d_in[14];
        att_b   = (const float*)d_in[15];
    } else {                        // signature order
        v_in    = (const float*)d_in[0];
        q_in    = (const float*)d_in[1];
        attn_w  = (const float*)d_in[2];
        attn_b  = (const float*)d_in[3];
        attn_wo = (const float*)d_in[4];
        attn_bo = (const float*)d_in[5];
        ln_g    = (const float*)d_in[6];
        ln_b    = (const float*)d_in[7];
        fw1     = (const float*)d_in[8];
        fb1     = (const float*)d_in[9];
        fw2     = (const float*)d_in[10];
        fb2     = (const float*)d_in[11];
        att_w   = (const float*)d_in[12];
        att_b   = (const float*)d_in[13];
        v_mask  = (const int*)  d_in[14];
        q_mask  = (const int*)  d_in[15];
    }

    float *V, *Q, *QKV, *SC, *AO, *TMP, *VA, *QA, *VQ, *QV, *FFN;
    cudaGetSymbolAddress((void**)&V,   g_v);
    cudaGetSymbolAddress((void**)&Q,   g_q);
    cudaGetSymbolAddress((void**)&QKV, g_qkv);
    cudaGetSymbolAddress((void**)&SC,  g_sc);
    cudaGetSymbolAddress((void**)&AO,  g_ao);
    cudaGetSymbolAddress((void**)&TMP, g_tmp);
    cudaGetSymbolAddress((void**)&VA,  g_va);
    cudaGetSymbolAddress((void**)&QA,  g_qa);
    cudaGetSymbolAddress((void**)&VQ,  g_vq);
    cudaGetSymbolAddress((void**)&QV,  g_qv);
    cudaGetSymbolAddress((void**)&FFN, g_ffn);

    const int NTOK = BB * NS * DM;
    const long long NT = (long long)NTOK;
    const long long SBATCH = (long long)NS * DM;
    copy_k<<<(NTOK + 255) / 256, 256>>>(v_in, V, NTOK);
    copy_k<<<(NTOK + 255) / 256, 256>>>(q_in, Q, NTOK);

    const int rows = BB * NS;

    for (int i = 0; i < NLAY; i++) {
        const float* aw  = attn_w  + (long long)i * 4 * 3 * DM * DM;
        const float* ab  = attn_b  + (long long)i * 4 * 3 * DM;
        const float* awo = attn_wo + (long long)i * 4 * DM * DM;
        const float* abo = attn_bo + (long long)i * 4 * DM;
        const float* lg  = ln_g + (long long)i * 6 * DM;
        const float* lb  = ln_b + (long long)i * 6 * DM;

        run_mha(V, V, v_mask, aw, ab, awo, abo, QKV, AO, TMP);
        ln_add<<<rows, 256>>>(V, TMP, lg, lb, VA);

        run_mha(Q, Q, q_mask,
                aw + 3ll * DM * DM, ab + 3 * DM, awo + (long long)DM * DM, abo + DM,
                QKV, AO, TMP);
        ln_add<<<rows, 256>>>(Q, TMP, lg + DM, lb + DM, QA);

        run_mha(VA, QA, q_mask,
                aw + 6ll * DM * DM, ab + 6 * DM, awo + 2ll * DM * DM, abo + 2 * DM,
                QKV, AO, VQ);
        run_mha(QA, VQ, v_mask,
                aw + 9ll * DM * DM, ab + 9 * DM, awo + 3ll * DM * DM, abo + 3 * DM,
                QKV, AO, QV);

        ln_add<<<rows, 256>>>(V, VQ, lg + 2 * DM, lb + 2 * DM, V);
        ln_add<<<rows, 256>>>(Q, QV, lg + 3 * DM, lb + 3 * DM, Q);

        const float* w1v = fw1 + (long long)i * 2 * DM * DFF;
        const float* b1v = fb1 + (long long)i * 2 * DFF;
        const float* w2v = fw2 + (long long)i * 2 * DFF * DM;
        const float* b2v = fb2 + (long long)i * 2 * DM;

        mma_nn2h<<<dim3(DFF / 128, rows / 64, 1), 128>>>(
            V, w1v, b1v, FFN, DM, DM, DFF, DFF,
            1, 0, 0, 0, 0, 0, 0, 0, 1);
        mma_nn2h<<<dim3(DM / 128, rows / 64, 1), 128>>>(
            FFN, w2v, b2v, TMP, DFF, DFF, DM, DM,
            1, 0, 0, 0, 0, 0, 0, 0, 0);
        ln_add<<<rows, 256>>>(V, TMP, lg + 4 * DM, lb + 4 * DM, V);

        mma_nn2h<<<dim3(DFF / 128, rows / 64, 1), 128>>>(
            Q, w1v + (long long)DM * DFF, b1v + DFF, FFN, DM, DM, DFF, DFF,
            1, 0, 0, 0, 0, 0, 0, 0, 1);
        mma_nn2h<<<dim3(DM / 128, rows / 64, 1), 128>>>(
            FFN, w2v + (long long)DFF * DM, b2v + DM, TMP, DFF, DFF, DM, DM,
            1, 0, 0, 0, 0, 0, 0, 0, 0);
        ln_add<<<rows, 256>>>(Q, TMP, lg + 5 * DM, lb + 5 * DM, Q);
    }

    // Final bilinear attention pooling.
    float* PQs = QKV;
    float* Ts  = QKV + NT;
    vmul_k<<<(NTOK + 255) / 256, 256>>>(V, att_w, PQs, NTOK);
    mma_nt2h<<<dim3(NS / 128, NS / 64, BB), 128>>>(
        PQs, Q, SC, DM, DM, DM, NS,
        1, SBATCH, 0, SBATCH, 0, (long long)NS * NS, 0, 1.0f);
    softmax_final<<<BB * NS, 256>>>(SC, v_mask, q_mask, att_b);
    mma_nn2h<<<dim3(DM / 128, NS / 64, BB), 128>>>(
        SC, Q, (const float*)nullptr, Ts, NS, NS, DM, DM,
        1, (long long)NS * NS, 0, SBATCH, 0, SBATCH, 0, 0, 0);
    final_out_k<<<BB, 512>>>(V, Ts, (float*)d_out);
}